// round 2
// baseline (speedup 1.0000x reference)
#include <cuda_runtime.h>

#define BSZ 8
#define SEQ 16
#define DIM 4096
#define NH 32
#define NKV 8
#define HD 128
#define CL 4096
#define NT (BSZ*SEQ)                 // 128 tokens
#define NQKV (DIM + 2*NKV*HD)        // 6144
#define ROPE_LIM (DIM + NKV*HD)      // 5120: q|k get rope, v doesn't
#define CACHE_ELEMS (BSZ*CL*NKV*HD)  // 33554432
#define CK_OFF ((size_t)NT*DIM)      // 524288
#define CV_OFF (CK_OFF + CACHE_ELEMS)
#define RSQRT_HD 0.08838834764831845f

typedef unsigned long long ull;

__device__ float g_qkv[(size_t)NT*NQKV];   // [128][6144]: q | k | v per token
__device__ float g_attn[(size_t)NT*DIM];   // [128][4096] attention output

// ---- packed f32x2 helpers -------------------------------------------------
__device__ __forceinline__ ull ffma2(ull a, ull b, ull c) {
    ull d;
    asm("fma.rn.f32x2 %0, %1, %2, %3;" : "=l"(d) : "l"(a), "l"(b), "l"(c));
    return d;
}
__device__ __forceinline__ ull pack2(float x, float y) {
    ull r; asm("mov.b64 %0, {%1, %2};" : "=l"(r) : "f"(x), "f"(y)); return r;
}
__device__ __forceinline__ float2 unpk(ull v) {
    float2 r; asm("mov.b64 {%0, %1}, %2;" : "=f"(r.x), "=f"(r.y) : "l"(v)); return r;
}

// ---------------------------------------------------------------------------
// GEMM: C[m][n] = sum_k A[m][k] * W[n][k]. BM=BN=64, BK=32, 256 thr, 4x4
// microtile, f32x2 packed FMA. W selected from up to 3 concatenated weight
// matrices (row boundaries at DIM and DIM+1024, both 64-aligned).
// Optional RoPE epilogue for cols < ropeLim (pairs are adjacent cols).
// ---------------------------------------------------------------------------
#define BK 32
__global__ __launch_bounds__(256) void gemm_f32x2(
    const float* __restrict__ A,
    const float* __restrict__ W0, const float* __restrict__ W1,
    const float* __restrict__ W2,
    float* __restrict__ C, int ldc,
    const float* __restrict__ freqs, int ropeLim)
{
    __shared__ float Xs[BK][64];
    __shared__ float Ws[BK][64];
    const int m0 = blockIdx.y * 64;
    const int n0 = blockIdx.x * 64;
    const int t  = threadIdx.x;
    const int tm = t >> 4, tn = t & 15;

    // pick weight matrix for this 64-row slice of the (possibly) fused N dim
    const float* W = W0; int nr = n0;
    if (W1 != nullptr && n0 >= DIM) {
        if (n0 < DIM + NKV*HD) { W = W1; nr = n0 - DIM; }
        else                   { W = W2; nr = n0 - DIM - NKV*HD; }
    }

    const int lr = t >> 2;      // row within 64-tile
    const int lq = t & 3;       // k-quarter (8 floats)
    const float* Ap = A + (size_t)(m0 + lr) * DIM + lq * 8;
    const float* Wp = W + (size_t)(nr + lr) * DIM + lq * 8;

    ull acc2[4][2] = {};

    float4 xa = *(const float4*)(Ap + 0);
    float4 xb = *(const float4*)(Ap + 4);
    float4 wa = *(const float4*)(Wp + 0);
    float4 wb = *(const float4*)(Wp + 4);

    for (int k0 = 0; k0 < DIM; k0 += BK) {
        __syncthreads();
        Xs[lq*8+0][lr]=xa.x; Xs[lq*8+1][lr]=xa.y; Xs[lq*8+2][lr]=xa.z; Xs[lq*8+3][lr]=xa.w;
        Xs[lq*8+4][lr]=xb.x; Xs[lq*8+5][lr]=xb.y; Xs[lq*8+6][lr]=xb.z; Xs[lq*8+7][lr]=xb.w;
        Ws[lq*8+0][lr]=wa.x; Ws[lq*8+1][lr]=wa.y; Ws[lq*8+2][lr]=wa.z; Ws[lq*8+3][lr]=wa.w;
        Ws[lq*8+4][lr]=wb.x; Ws[lq*8+5][lr]=wb.y; Ws[lq*8+6][lr]=wb.z; Ws[lq*8+7][lr]=wb.w;
        __syncthreads();

        int kn = (k0 + BK < DIM) ? (k0 + BK) : 0;   // safe prefetch
        xa = *(const float4*)(Ap + kn);
        xb = *(const float4*)(Ap + kn + 4);
        wa = *(const float4*)(Wp + kn);
        wb = *(const float4*)(Wp + kn + 4);

        #pragma unroll
        for (int k = 0; k < BK; k++) {
            float4 a = *(const float4*)&Xs[k][tm*4];
            ulonglong2 b = *(const ulonglong2*)&Ws[k][tn*4];
            ull a0 = pack2(a.x, a.x), a1 = pack2(a.y, a.y);
            ull a2 = pack2(a.z, a.z), a3 = pack2(a.w, a.w);
            acc2[0][0] = ffma2(a0, b.x, acc2[0][0]); acc2[0][1] = ffma2(a0, b.y, acc2[0][1]);
            acc2[1][0] = ffma2(a1, b.x, acc2[1][0]); acc2[1][1] = ffma2(a1, b.y, acc2[1][1]);
            acc2[2][0] = ffma2(a2, b.x, acc2[2][0]); acc2[2][1] = ffma2(a2, b.y, acc2[2][1]);
            acc2[3][0] = ffma2(a3, b.x, acc2[3][0]); acc2[3][1] = ffma2(a3, b.y, acc2[3][1]);
        }
    }

    const int col = n0 + tn*4;
    const bool doRope = col < ropeLim;
    const int pd2 = (col & (HD-1)) >> 1;   // pair index within head for col,col+1
    #pragma unroll
    for (int i = 0; i < 4; i++) {
        float2 p0 = unpk(acc2[i][0]);
        float2 p1 = unpk(acc2[i][1]);
        float4 o;
        if (doRope) {
            int s = (m0 + tm*4 + i) & (SEQ-1);
            const float* f = freqs + s*128 + pd2*2;   // [cos0,sin0,cos1,sin1]
            float c0 = f[0], s0 = f[1], c1 = f[2], s1 = f[3];
            o.x = p0.x*c0 - p0.y*s0;  o.y = p0.x*s0 + p0.y*c0;
            o.z = p1.x*c1 - p1.y*s1;  o.w = p1.x*s1 + p1.y*c1;
        } else {
            o.x = p0.x; o.y = p0.y; o.z = p1.x; o.w = p1.y;
        }
        *(float4*)&C[(size_t)(m0 + tm*4 + i) * ldc + col] = o;
    }
}

// ---------------------------------------------------------------------------
// Cache shift + append: cout[b][t] = cin[b][t+16] for t<4080, else new k/v
// (already RoPE'd in g_qkv). float4 throughout.
// ---------------------------------------------------------------------------
__global__ __launch_bounds__(256) void cache_update(
    const float* __restrict__ cin, float* __restrict__ cout,
    const float* __restrict__ src /* g_qkv + col offset of k or v */)
{
    const int total = CACHE_ELEMS / 4;           // 8388608 float4
    int i = blockIdx.x * 256 + threadIdx.x;
    if (i >= total) return;
    const int ROW4 = NKV * HD / 4;               // 256 float4 per t-row
    int b    = i / (CL * ROW4);
    int r    = i % (CL * ROW4);
    int tpos = r / ROW4;
    int c    = r % ROW4;
    float4 v;
    if (tpos < CL - SEQ) {
        v = ((const float4*)cin)[(size_t)(b * CL + tpos + SEQ) * ROW4 + c];
    } else {
        int s   = tpos - (CL - SEQ);
        int tok = b * SEQ + s;
        v = *(const float4*)(src + (size_t)tok * NQKV + c * 4);
    }
    ((float4*)cout)[i] = v;
}

// ---------------------------------------------------------------------------
// Attention: one block per (b, h). 256 threads, 512-key chunks, online
// softmax. Phase 1 uses f32x2 packed FMA over a transposed q tile.
// ---------------------------------------------------------------------------
#define CHUNK 512
__global__ __launch_bounds__(256) void attn_kernel(
    const float* __restrict__ qkv, const float* __restrict__ Kc,
    const float* __restrict__ Vc, const float* __restrict__ mask,
    float* __restrict__ attn_out)
{
    __shared__ float q_t[HD][SEQ];        // transposed, pre-scaled. 8 KB
    __shared__ float s_s[SEQ][CHUNK];     // 32 KB
    __shared__ float m_s[SEQ], l_s[SEQ], sc_s[SEQ];

    const int t   = threadIdx.x;
    const int b   = blockIdx.x / NH;
    const int h   = blockIdx.x % NH;
    const int kvh = h >> 2;               // n_rep = 4

    for (int i = t; i < SEQ * HD; i += 256) {
        int s = i >> 7, d = i & (HD-1);
        q_t[d][s] = qkv[(size_t)(b*SEQ + s) * NQKV + h*HD + d] * RSQRT_HD;
    }
    if (t < SEQ) { m_s[t] = -1e30f; l_s[t] = 0.f; }
    __syncthreads();

    const int dp = t & 63;                // d = 2*dp, 2*dp+1
    const int qg = t >> 6;                // queries qg*4 .. qg*4+3
    float acc[4][2] = {};

    const float* Kb = Kc + (size_t)b * CL * (NKV*HD) + kvh * HD;
    const float* Vb = Vc + (size_t)b * CL * (NKV*HD) + kvh * HD;

    for (int c0 = 0; c0 < CL; c0 += CHUNK) {
        // ---- Phase 1: scores for keys c0+t and c0+t+256 (f32x2) ----
        {
            const float* kA = Kb + (size_t)(c0 + t) * (NKV*HD);
            const float* kB = kA + (size_t)256 * (NKV*HD);
            ull dA[8] = {}, dB[8] = {};   // 8 q-pairs each
            #pragma unroll 2
            for (int d0 = 0; d0 < HD; d0 += 4) {
                float4 a4 = *(const float4*)(kA + d0);
                float4 b4 = *(const float4*)(kB + d0);
                #pragma unroll
                for (int dd = 0; dd < 4; dd++) {
                    float av = (&a4.x)[dd];
                    float bv = (&b4.x)[dd];
                    ull ap = pack2(av, av);
                    ull bp = pack2(bv, bv);
                    const ulonglong2* qr = (const ulonglong2*)&q_t[d0+dd][0];
                    #pragma unroll
                    for (int p = 0; p < 4; p++) {
                        ulonglong2 qq = qr[p];
                        dA[2*p+0] = ffma2(ap, qq.x, dA[2*p+0]);
                        dA[2*p+1] = ffma2(ap, qq.y, dA[2*p+1]);
                        dB[2*p+0] = ffma2(bp, qq.x, dB[2*p+0]);
                        dB[2*p+1] = ffma2(bp, qq.y, dB[2*p+1]);
                    }
                }
            }
            #pragma unroll
            for (int p = 0; p < 8; p++) {
                float2 va = unpk(dA[p]);
                float2 vb = unpk(dB[p]);
                s_s[2*p+0][t]       = va.x + mask[(2*p+0)*CL + c0 + t];
                s_s[2*p+1][t]       = va.y + mask[(2*p+1)*CL + c0 + t];
                s_s[2*p+0][t + 256] = vb.x + mask[(2*p+0)*CL + c0 + t + 256];
                s_s[2*p+1][t + 256] = vb.y + mask[(2*p+1)*CL + c0 + t + 256];
            }
        }
        __syncthreads();

        // ---- Phase 2: online softmax update (warp w -> rows 2w, 2w+1) ----
        {
            int w = t >> 5, lane = t & 31;
            for (int rr = 0; rr < 2; rr++) {
                int q = w*2 + rr;
                float mx = -1e30f;
                for (int j = lane; j < CHUNK; j += 32) mx = fmaxf(mx, s_s[q][j]);
                #pragma unroll
                for (int o = 16; o; o >>= 1) mx = fmaxf(mx, __shfl_xor_sync(0xffffffffu, mx, o));
                float mnew = fmaxf(m_s[q], mx);
                float sum = 0.f;
                for (int j = lane; j < CHUNK; j += 32) {
                    float p = __expf(s_s[q][j] - mnew);
                    s_s[q][j] = p;
                    sum += p;
                }
                #pragma unroll
                for (int o = 16; o; o >>= 1) sum += __shfl_xor_sync(0xffffffffu, sum, o);
                if (lane == 0) {
                    float sc = __expf(m_s[q] - mnew);
                    sc_s[q] = sc;
                    l_s[q]  = l_s[q] * sc + sum;
                    m_s[q]  = mnew;
                }
            }
        }
        __syncthreads();

        // ---- Phase 3: P @ V accumulation ----
        #pragma unroll
        for (int i = 0; i < 4; i++) {
            float sc = sc_s[qg*4 + i];
            acc[i][0] *= sc; acc[i][1] *= sc;
        }
        const float* vrow = Vb + (size_t)c0 * (NKV*HD) + 2*dp;
        for (int j0 = 0; j0 < CHUNK; j0 += 4) {
            float2 v0 = *(const float2*)(vrow + (size_t)(j0+0) * (NKV*HD));
            float2 v1 = *(const float2*)(vrow + (size_t)(j0+1) * (NKV*HD));
            float2 v2 = *(const float2*)(vrow + (size_t)(j0+2) * (NKV*HD));
            float2 v3 = *(const float2*)(vrow + (size_t)(j0+3) * (NKV*HD));
            #pragma unroll
            for (int i = 0; i < 4; i++) {
                float4 p = *(const float4*)&s_s[qg*4 + i][j0];
                acc[i][0] += p.x*v0.x + p.y*v1.x + p.z*v2.x + p.w*v3.x;
                acc[i][1] += p.x*v0.y + p.y*v1.y + p.z*v2.y + p.w*v3.y;
            }
        }
        __syncthreads();   // s_s reused next chunk
    }

    #pragma unroll
    for (int i = 0; i < 4; i++) {
        int q = qg*4 + i;
        float inv = 1.f / l_s[q];
        int tok = b*SEQ + q;
        attn_out[(size_t)tok * DIM + h*HD + 2*dp + 0] = acc[i][0] * inv;
        attn_out[(size_t)tok * DIM + h*HD + 2*dp + 1] = acc[i][1] * inv;
    }
}

// ---------------------------------------------------------------------------
extern "C" void kernel_launch(void* const* d_in, const int* in_sizes, int n_in,
                              void* d_out, int out_size)
{
    const float* x     = (const float*)d_in[0];
    const float* mask  = (const float*)d_in[1];
    const float* freqs = (const float*)d_in[2];
    const float* ck    = (const float*)d_in[3];
    const float* cv    = (const float*)d_in[4];
    const float* wq    = (const float*)d_in[5];
    const float* wk    = (const float*)d_in[6];
    const float* wv    = (const float*)d_in[7];
    const float* wo    = (const float*)d_in[8];
    float* out = (float*)d_out;

    float *qkv, *attn;
    cudaGetSymbolAddress((void**)&qkv, g_qkv);
    cudaGetSymbolAddress((void**)&attn, g_attn);

    // Fused QKV projection with RoPE epilogue (q and k columns only)
    gemm_f32x2<<<dim3(NQKV/64, 2), 256>>>(x, wq, wk, wv, qkv, NQKV, freqs, ROPE_LIM);

    // Cache shift + append (writes cache_k / cache_v outputs)
    int cb = (CACHE_ELEMS/4 + 255) / 256;
    cache_update<<<cb, 256>>>(ck, out + CK_OFF, qkv + DIM);
    cache_update<<<cb, 256>>>(cv, out + CV_OFF, qkv + DIM + NKV*HD);

    // Attention over the updated caches
    attn_kernel<<<BSZ*NH, 256>>>(qkv, out + CK_OFF, out + CV_OFF, mask, attn);

    // Output projection
    gemm_f32x2<<<dim3(DIM/64, 2), 256>>>(attn, wo, nullptr, nullptr, out, DIM, nullptr, 0);
}

// round 3
// speedup vs baseline: 1.0183x; 1.0183x over previous
#include <cuda_runtime.h>

#define BSZ 8
#define SEQ 16
#define DIM 4096
#define NH 32
#define NKV 8
#define HD 128
#define CL 4096
#define NT (BSZ*SEQ)                 // 128 tokens
#define NQKV (DIM + 2*NKV*HD)        // 6144
#define ROPE_LIM (DIM + NKV*HD)      // 5120
#define CACHE_ELEMS (BSZ*CL*NKV*HD)
#define CK_OFF ((size_t)NT*DIM)
#define CV_OFF (CK_OFF + CACHE_ELEMS)
#define RSQRT_HD 0.08838834764831845f
#define NSPLIT 8
#define KEYS_PER_SPLIT (CL/NSPLIT)   // 512

typedef unsigned long long ull;

__device__ float g_qkv[(size_t)NT*NQKV];
__device__ float g_attn[(size_t)NT*DIM];
__device__ float g_po[(size_t)BSZ*NKV*NSPLIT*64*128];   // partial O
__device__ float g_pml[(size_t)BSZ*NKV*NSPLIT*64*2];    // partial m,l

// ---- packed f32x2 helpers -------------------------------------------------
__device__ __forceinline__ ull ffma2(ull a, ull b, ull c) {
    ull d; asm("fma.rn.f32x2 %0, %1, %2, %3;" : "=l"(d) : "l"(a), "l"(b), "l"(c));
    return d;
}
__device__ __forceinline__ ull addf2(ull a, ull b) {
    ull d; asm("add.rn.f32x2 %0, %1, %2;" : "=l"(d) : "l"(a), "l"(b)); return d;
}
__device__ __forceinline__ ull mulf2(ull a, ull b) {
    ull d; asm("mul.rn.f32x2 %0, %1, %2;" : "=l"(d) : "l"(a), "l"(b)); return d;
}
__device__ __forceinline__ ull pack2(float x, float y) {
    ull r; asm("mov.b64 %0, {%1, %2};" : "=l"(r) : "f"(x), "f"(y)); return r;
}
__device__ __forceinline__ float2 unpk(ull v) {
    float2 r; asm("mov.b64 {%0, %1}, %2;" : "=f"(r.x), "=f"(r.y) : "l"(v)); return r;
}

// ---------------------------------------------------------------------------
// GEMM: C[m][n] = sum_k A[m][k]*W[n][k].  BM=64, BN=64, BK=16, 256 threads.
// W pre-duplicated into smem as (w,w) ull; A rows M-contiguous so adjacent-M
// pairs are natural LDS.128 halves. Thread: 2 m-pairs x 4 n = 16 MACs/k via
// 8 FFMA2 + 3 LDS.128.  Optional RoPE epilogue; W selected from fused QKV.
// ---------------------------------------------------------------------------
#define GBK 16
__global__ __launch_bounds__(256) void gemm_f32x2(
    const float* __restrict__ A,
    const float* __restrict__ W0, const float* __restrict__ W1,
    const float* __restrict__ W2,
    float* __restrict__ C, int ldc,
    const float* __restrict__ freqs, int ropeLim)
{
    __shared__ float Xs[GBK][68];
    __shared__ ull   Ws2[GBK][66];
    const int m0 = blockIdx.y * 64;
    const int n0 = blockIdx.x * 64;
    const int t  = threadIdx.x;
    const int tm = t >> 4, tn = t & 15;

    const float* W = W0; int nr = n0;
    if (W1 != nullptr && n0 >= DIM) {
        if (n0 < DIM + NKV*HD) { W = W1; nr = n0 - DIM; }
        else                   { W = W2; nr = n0 - DIM - NKV*HD; }
    }

    const int lr = t >> 2;      // row within 64
    const int lq = t & 3;       // k-quarter (4 floats)
    const float* Ap = A + (size_t)(m0 + lr) * DIM + lq * 4;
    const float* Wp = W + (size_t)(nr + lr) * DIM + lq * 4;

    ull acc[2][4] = {};

    float4 xa = *(const float4*)(Ap);
    float4 wa = *(const float4*)(Wp);

    for (int k0 = 0; k0 < DIM; k0 += GBK) {
        __syncthreads();
        Xs[lq*4+0][lr] = xa.x; Xs[lq*4+1][lr] = xa.y;
        Xs[lq*4+2][lr] = xa.z; Xs[lq*4+3][lr] = xa.w;
        Ws2[lq*4+0][lr] = pack2(wa.x, wa.x);
        Ws2[lq*4+1][lr] = pack2(wa.y, wa.y);
        Ws2[lq*4+2][lr] = pack2(wa.z, wa.z);
        Ws2[lq*4+3][lr] = pack2(wa.w, wa.w);
        __syncthreads();

        int kn = (k0 + GBK < DIM) ? (k0 + GBK) : 0;   // safe prefetch
        xa = *(const float4*)(Ap + kn - 0) ;
        xa = *(const float4*)(Ap + kn);
        wa = *(const float4*)(Wp + kn);

        #pragma unroll
        for (int k = 0; k < GBK; k++) {
            ulonglong2 a  = *(const ulonglong2*)&Xs[k][tm*4];     // 2 m-pairs
            ulonglong2 b01 = *(const ulonglong2*)&Ws2[k][tn*4];
            ulonglong2 b23 = *(const ulonglong2*)&Ws2[k][tn*4+2];
            acc[0][0] = ffma2(a.x, b01.x, acc[0][0]);
            acc[0][1] = ffma2(a.x, b01.y, acc[0][1]);
            acc[0][2] = ffma2(a.x, b23.x, acc[0][2]);
            acc[0][3] = ffma2(a.x, b23.y, acc[0][3]);
            acc[1][0] = ffma2(a.y, b01.x, acc[1][0]);
            acc[1][1] = ffma2(a.y, b01.y, acc[1][1]);
            acc[1][2] = ffma2(a.y, b23.x, acc[1][2]);
            acc[1][3] = ffma2(a.y, b23.y, acc[1][3]);
        }
    }

    // epilogue: rows m0+tm*4+{0..3}; cols n0+tn*4..+3; optional rope
    const int col = n0 + tn*4;
    const bool doRope = col < ropeLim;
    const int pd2 = (col & (HD-1)) >> 1;
    #pragma unroll
    for (int mp = 0; mp < 2; mp++) {
        float2 c0 = unpk(acc[mp][0]);
        float2 c1 = unpk(acc[mp][1]);
        float2 c2 = unpk(acc[mp][2]);
        float2 c3 = unpk(acc[mp][3]);
        #pragma unroll
        for (int half = 0; half < 2; half++) {
            int row = m0 + tm*4 + mp*2 + half;
            float v0 = half ? c0.y : c0.x;
            float v1 = half ? c1.y : c1.x;
            float v2 = half ? c2.y : c2.x;
            float v3 = half ? c3.y : c3.x;
            float4 o;
            if (doRope) {
                int s = row & (SEQ-1);
                const float* f = freqs + s*128 + pd2*2;
                float ca = f[0], sa = f[1], cb = f[2], sb = f[3];
                o.x = v0*ca - v1*sa;  o.y = v0*sa + v1*ca;
                o.z = v2*cb - v3*sb;  o.w = v2*sb + v3*cb;
            } else {
                o.x = v0; o.y = v1; o.z = v2; o.w = v3;
            }
            *(float4*)&C[(size_t)row * ldc + col] = o;
        }
    }
}

// ---------------------------------------------------------------------------
// Cache shift + append (unchanged)
// ---------------------------------------------------------------------------
__global__ __launch_bounds__(256) void cache_update(
    const float* __restrict__ cin, float* __restrict__ cout,
    const float* __restrict__ src)
{
    const int total = CACHE_ELEMS / 4;
    int i = blockIdx.x * 256 + threadIdx.x;
    if (i >= total) return;
    const int ROW4 = NKV * HD / 4;
    int b    = i / (CL * ROW4);
    int r    = i % (CL * ROW4);
    int tpos = r / ROW4;
    int c    = r % ROW4;
    float4 v;
    if (tpos < CL - SEQ) {
        v = ((const float4*)cin)[(size_t)(b * CL + tpos + SEQ) * ROW4 + c];
    } else {
        int s   = tpos - (CL - SEQ);
        int tok = b * SEQ + s;
        v = *(const float4*)(src + (size_t)tok * NQKV + c * 4);
    }
    ((float4*)cout)[i] = v;
}

// ---------------------------------------------------------------------------
// Attention, grouped + split-KV.
// grid = (NSPLIT, NKV, BSZ); block = 256. Each block: 64 q (4 heads x 16 seq)
// over 512 keys in 128-key chunks. Outputs unnormalized partials + (m,l).
// Smem (floats): q_t[128][66], s_t[128][66], mask_t[128][18], m/l/sc[64].
// ---------------------------------------------------------------------------
__global__ __launch_bounds__(256, 2) void attn_kernel(
    const float* __restrict__ qkv, const float* __restrict__ Kc,
    const float* __restrict__ Vc, const float* __restrict__ mask,
    float* __restrict__ po, float* __restrict__ pml)
{
    extern __shared__ float smf[];
    float* q_t    = smf;                 // [128][66]
    float* s_t    = smf + 8448;          // [128][66]
    float* mask_t = smf + 16896;         // [128][18]
    float* m_s    = smf + 19200;         // [64]
    float* l_s    = smf + 19264;         // [64]
    float* sc_s   = smf + 19328;         // [64]

    const int t   = threadIdx.x;
    const int sp  = blockIdx.x;
    const int kvh = blockIdx.y;
    const int b   = blockIdx.z;

    for (int i = t; i < 64*HD; i += 256) {
        int d = i & (HD-1), q = i >> 7;
        int s = q & 15, hh = q >> 4;
        q_t[d*66 + q] = qkv[(size_t)(b*SEQ+s)*NQKV + (kvh*4+hh)*HD + d] * RSQRT_HD;
    }
    if (t < 64) { m_s[t] = -1e30f; l_s[t] = 0.f; }

    const int key0 = sp * KEYS_PER_SPLIT;
    const int hh1  = t >> 6;       // phase1 head
    const int kk   = t & 63;       // phase1 key
    const int dpd  = t & 127;      // phase3 d
    const int qh   = t >> 7;       // phase3 q-half
    ull acc[16] = {};

    for (int c0 = 0; c0 < KEYS_PER_SPLIT; c0 += 128) {
        // stage mask chunk transposed
        for (int i = t; i < 16*128; i += 256) {
            int s = i >> 7, k = i & 127;
            mask_t[k*18 + s] = mask[s*CL + key0 + c0 + k];
        }
        __syncthreads();

        // ---- Phase 1: QK scores (pairs over q) ----
        {
            int gA = key0 + c0 + kk, gB = gA + 64;
            const float* KA = Kc + ((size_t)(b*CL + gA)*NKV + kvh)*HD;
            const float* KB = Kc + ((size_t)(b*CL + gB)*NKV + kvh)*HD;
            ull accA[8] = {}, accB[8] = {};
            #pragma unroll 4
            for (int d0 = 0; d0 < HD; d0 += 4) {
                float4 a4 = *(const float4*)(KA + d0);
                float4 b4 = *(const float4*)(KB + d0);
                #pragma unroll
                for (int dd = 0; dd < 4; dd++) {
                    float av = (&a4.x)[dd], bv = (&b4.x)[dd];
                    ull ad = pack2(av, av);
                    ull bd = pack2(bv, bv);
                    const ull* qr = (const ull*)(q_t + (d0+dd)*66 + hh1*16);
                    #pragma unroll
                    for (int i = 0; i < 8; i++) accA[i] = ffma2(ad, qr[i], accA[i]);
                    #pragma unroll
                    for (int i = 0; i < 8; i++) accB[i] = ffma2(bd, qr[i], accB[i]);
                }
            }
            #pragma unroll
            for (int i = 0; i < 8; i++) {
                ull mA = *(const ull*)(mask_t + kk*18 + 2*i);
                ull mB = *(const ull*)(mask_t + (kk+64)*18 + 2*i);
                *(ull*)(s_t + kk*66      + hh1*16 + 2*i) = addf2(accA[i], mA);
                *(ull*)(s_t + (kk+64)*66 + hh1*16 + 2*i) = addf2(accB[i], mB);
            }
        }
        __syncthreads();

        // ---- Phase 2: online softmax (warp w -> q = w*8..w*8+7) ----
        {
            int w = t >> 5, lane = t & 31;
            #pragma unroll
            for (int rr = 0; rr < 8; rr++) {
                int q = w*8 + rr;
                float v0 = s_t[(lane+ 0)*66 + q];
                float v1 = s_t[(lane+32)*66 + q];
                float v2 = s_t[(lane+64)*66 + q];
                float v3 = s_t[(lane+96)*66 + q];
                float mx = fmaxf(fmaxf(v0,v1), fmaxf(v2,v3));
                #pragma unroll
                for (int o = 16; o; o >>= 1) mx = fmaxf(mx, __shfl_xor_sync(0xffffffffu, mx, o));
                float mnew = fmaxf(m_s[q], mx);
                float p0 = __expf(v0 - mnew), p1 = __expf(v1 - mnew);
                float p2 = __expf(v2 - mnew), p3 = __expf(v3 - mnew);
                s_t[(lane+ 0)*66 + q] = p0;
                s_t[(lane+32)*66 + q] = p1;
                s_t[(lane+64)*66 + q] = p2;
                s_t[(lane+96)*66 + q] = p3;
                float sum = (p0+p1) + (p2+p3);
                #pragma unroll
                for (int o = 16; o; o >>= 1) sum += __shfl_xor_sync(0xffffffffu, sum, o);
                if (lane == 0) {
                    float sc = __expf(m_s[q] - mnew);
                    sc_s[q] = sc;
                    l_s[q]  = l_s[q] * sc + sum;
                    m_s[q]  = mnew;
                }
            }
        }
        __syncthreads();

        // ---- Phase 3: P @ V (pairs over q) ----
        {
            #pragma unroll
            for (int i = 0; i < 16; i++) {
                ull scp = *(const ull*)(sc_s + qh*32 + 2*i);
                acc[i] = mulf2(acc[i], scp);
            }
            const float* Vp = Vc + ((size_t)(b*CL + key0 + c0)*NKV + kvh)*HD + dpd;
            #pragma unroll 2
            for (int k = 0; k < 128; k += 2) {
                float va = Vp[(size_t)(k+0)*NKV*HD];
                float vb = Vp[(size_t)(k+1)*NKV*HD];
                ull vda = pack2(va, va);
                ull vdb = pack2(vb, vb);
                const ull* pra = (const ull*)(s_t + (k+0)*66 + qh*32);
                const ull* prb = (const ull*)(s_t + (k+1)*66 + qh*32);
                #pragma unroll
                for (int i = 0; i < 16; i++) acc[i] = ffma2(vda, pra[i], acc[i]);
                #pragma unroll
                for (int i = 0; i < 16; i++) acc[i] = ffma2(vdb, prb[i], acc[i]);
            }
        }
        __syncthreads();
    }

    // write partials
    size_t base = ((size_t)(b*NKV + kvh)*NSPLIT + sp)*64;
    #pragma unroll
    for (int i = 0; i < 16; i++) {
        float2 v = unpk(acc[i]);
        int q0 = qh*32 + 2*i;
        po[(base + q0  )*128 + dpd] = v.x;
        po[(base + q0+1)*128 + dpd] = v.y;
    }
    if (t < 64) {
        pml[(base + t)*2 + 0] = m_s[t];
        pml[(base + t)*2 + 1] = l_s[t];
    }
}

// ---------------------------------------------------------------------------
// Combine split-KV partials -> attn output [tok][DIM]
// ---------------------------------------------------------------------------
__global__ __launch_bounds__(256) void attn_combine(
    const float* __restrict__ po, const float* __restrict__ pml,
    float* __restrict__ attn_out)
{
    __shared__ float wsm[NSPLIT][64];
    __shared__ float linv[64];
    const int t  = threadIdx.x;
    const int bk = blockIdx.x;           // b*NKV + kvh
    if (t < 64) {
        float mv[NSPLIT];
        float M = -1e30f;
        #pragma unroll
        for (int i = 0; i < NSPLIT; i++) {
            mv[i] = pml[((size_t)(bk*NSPLIT + i)*64 + t)*2 + 0];
            M = fmaxf(M, mv[i]);
        }
        float L = 0.f;
        #pragma unroll
        for (int i = 0; i < NSPLIT; i++) {
            float w = __expf(mv[i] - M);
            wsm[i][t] = w;
            L += w * pml[((size_t)(bk*NSPLIT + i)*64 + t)*2 + 1];
        }
        linv[t] = 1.f / L;
    }
    __syncthreads();
    const int d  = t & 127;
    const int qh = t >> 7;
    const int b = bk >> 3, kvh = bk & 7;
    for (int q = qh*32; q < qh*32 + 32; q++) {
        float o = 0.f;
        #pragma unroll
        for (int i = 0; i < NSPLIT; i++)
            o += po[((size_t)(bk*NSPLIT + i)*64 + q)*128 + d] * wsm[i][q];
        o *= linv[q];
        int s = q & 15, hh = q >> 4;
        attn_out[(size_t)(b*SEQ + s)*DIM + (kvh*4 + hh)*HD + d] = o;
    }
}

// ---------------------------------------------------------------------------
extern "C" void kernel_launch(void* const* d_in, const int* in_sizes, int n_in,
                              void* d_out, int out_size)
{
    const float* x     = (const float*)d_in[0];
    const float* mask  = (const float*)d_in[1];
    const float* freqs = (const float*)d_in[2];
    const float* ck    = (const float*)d_in[3];
    const float* cv    = (const float*)d_in[4];
    const float* wq    = (const float*)d_in[5];
    const float* wk    = (const float*)d_in[6];
    const float* wv    = (const float*)d_in[7];
    const float* wo    = (const float*)d_in[8];
    float* out = (float*)d_out;

    float *qkv, *attn, *po, *pml;
    cudaGetSymbolAddress((void**)&qkv,  g_qkv);
    cudaGetSymbolAddress((void**)&attn, g_attn);
    cudaGetSymbolAddress((void**)&po,   g_po);
    cudaGetSymbolAddress((void**)&pml,  g_pml);

    static int smem_set = 0;
    const int attn_smem = 19392 * sizeof(float);   // 77568 B
    if (!smem_set) {
        cudaFuncSetAttribute(attn_kernel, cudaFuncAttributeMaxDynamicSharedMemorySize, attn_smem);
        smem_set = 1;
    }

    // Fused QKV projection + RoPE epilogue
    gemm_f32x2<<<dim3(NQKV/64, 2), 256>>>(x, wq, wk, wv, qkv, NQKV, freqs, ROPE_LIM);

    // Cache shift + append
    int cb = (CACHE_ELEMS/4 + 255) / 256;
    cache_update<<<cb, 256>>>(ck, out + CK_OFF, qkv + DIM);
    cache_update<<<cb, 256>>>(cv, out + CV_OFF, qkv + DIM + NKV*HD);

    // Attention (split-KV) + combine
    attn_kernel<<<dim3(NSPLIT, NKV, BSZ), 256, attn_smem>>>(
        qkv, out + CK_OFF, out + CV_OFF, mask, po, pml);
    attn_combine<<<BSZ*NKV, 256>>>(po, pml, attn);

    // Output projection
    gemm_f32x2<<<dim3(DIM/64, 2), 256>>>(attn, wo, nullptr, nullptr, out, DIM, nullptr, 0);
}

// round 4
// speedup vs baseline: 1.4789x; 1.4523x over previous
#include <cuda_runtime.h>

#define BSZ 8
#define SEQ 16
#define DIM 4096
#define NH 32
#define NKV 8
#define HD 128
#define CL 4096
#define NT (BSZ*SEQ)                 // 128 tokens
#define NQKV (DIM + 2*NKV*HD)        // 6144
#define ROPE_LIM (DIM + NKV*HD)      // 5120
#define CACHE_ELEMS (BSZ*CL*NKV*HD)
#define CK_OFF ((size_t)NT*DIM)
#define CV_OFF (CK_OFF + CACHE_ELEMS)
#define RSQRT_HD 0.08838834764831845f
#define NSPLIT 8
#define KEYS_PER_SPLIT (CL/NSPLIT)   // 512

typedef unsigned long long ull;

__device__ float g_qkv[(size_t)NT*NQKV];
__device__ float g_attn[(size_t)NT*DIM];
__device__ float g_po[(size_t)BSZ*NKV*NSPLIT*64*128];   // partial O
__device__ float g_pml[(size_t)BSZ*NKV*NSPLIT*64*2];    // partial m,l

// ---- packed f32x2 helpers (attention only) --------------------------------
__device__ __forceinline__ ull ffma2(ull a, ull b, ull c) {
    ull d; asm("fma.rn.f32x2 %0, %1, %2, %3;" : "=l"(d) : "l"(a), "l"(b), "l"(c));
    return d;
}
__device__ __forceinline__ ull addf2(ull a, ull b) {
    ull d; asm("add.rn.f32x2 %0, %1, %2;" : "=l"(d) : "l"(a), "l"(b)); return d;
}
__device__ __forceinline__ ull mulf2(ull a, ull b) {
    ull d; asm("mul.rn.f32x2 %0, %1, %2;" : "=l"(d) : "l"(a), "l"(b)); return d;
}
__device__ __forceinline__ ull pack2(float x, float y) {
    ull r; asm("mov.b64 %0, {%1, %2};" : "=l"(r) : "f"(x), "f"(y)); return r;
}
__device__ __forceinline__ float2 unpk(ull v) {
    float2 r; asm("mov.b64 {%0, %1}, %2;" : "=f"(r.x), "=f"(r.y) : "l"(v)); return r;
}

// ---------------------------------------------------------------------------
// GEMM (scalar FFMA, R1-proven): C[m][n] = sum_k A[m][k] * W[n][k].
// BM=BN=64, BK=32, 256 threads, 4x4 microtile, register prefetch.
// W selected from up to 3 fused weight matrices; optional RoPE epilogue.
// ---------------------------------------------------------------------------
#define BK 32
__global__ __launch_bounds__(256) void gemm_tn(
    const float* __restrict__ A,
    const float* __restrict__ W0, const float* __restrict__ W1,
    const float* __restrict__ W2,
    float* __restrict__ C, int ldc,
    const float* __restrict__ freqs, int ropeLim)
{
    __shared__ float Xs[BK][64];
    __shared__ float Ws[BK][64];
    const int m0 = blockIdx.y * 64;
    const int n0 = blockIdx.x * 64;
    const int t  = threadIdx.x;
    const int tm = t >> 4, tn = t & 15;

    const float* W = W0; int nr = n0;
    if (W1 != nullptr && n0 >= DIM) {
        if (n0 < DIM + NKV*HD) { W = W1; nr = n0 - DIM; }
        else                   { W = W2; nr = n0 - DIM - NKV*HD; }
    }

    const int lr = t >> 2;      // row within 64-tile
    const int lq = t & 3;       // k-quarter (8 floats)
    const float* Ap = A + (size_t)(m0 + lr) * DIM + lq * 8;
    const float* Wp = W + (size_t)(nr + lr) * DIM + lq * 8;

    float acc[4][4] = {};

    float4 xa = *(const float4*)(Ap + 0);
    float4 xb = *(const float4*)(Ap + 4);
    float4 wa = *(const float4*)(Wp + 0);
    float4 wb = *(const float4*)(Wp + 4);

    for (int k0 = 0; k0 < DIM; k0 += BK) {
        __syncthreads();
        Xs[lq*8+0][lr]=xa.x; Xs[lq*8+1][lr]=xa.y; Xs[lq*8+2][lr]=xa.z; Xs[lq*8+3][lr]=xa.w;
        Xs[lq*8+4][lr]=xb.x; Xs[lq*8+5][lr]=xb.y; Xs[lq*8+6][lr]=xb.z; Xs[lq*8+7][lr]=xb.w;
        Ws[lq*8+0][lr]=wa.x; Ws[lq*8+1][lr]=wa.y; Ws[lq*8+2][lr]=wa.z; Ws[lq*8+3][lr]=wa.w;
        Ws[lq*8+4][lr]=wb.x; Ws[lq*8+5][lr]=wb.y; Ws[lq*8+6][lr]=wb.z; Ws[lq*8+7][lr]=wb.w;
        __syncthreads();

        int kn = (k0 + BK < DIM) ? (k0 + BK) : 0;   // safe prefetch
        xa = *(const float4*)(Ap + kn);
        xb = *(const float4*)(Ap + kn + 4);
        wa = *(const float4*)(Wp + kn);
        wb = *(const float4*)(Wp + kn + 4);

        #pragma unroll
        for (int k = 0; k < BK; k++) {
            float4 a = *(const float4*)&Xs[k][tm*4];
            float4 b = *(const float4*)&Ws[k][tn*4];
            acc[0][0] += a.x*b.x; acc[0][1] += a.x*b.y; acc[0][2] += a.x*b.z; acc[0][3] += a.x*b.w;
            acc[1][0] += a.y*b.x; acc[1][1] += a.y*b.y; acc[1][2] += a.y*b.z; acc[1][3] += a.y*b.w;
            acc[2][0] += a.z*b.x; acc[2][1] += a.z*b.y; acc[2][2] += a.z*b.z; acc[2][3] += a.z*b.w;
            acc[3][0] += a.w*b.x; acc[3][1] += a.w*b.y; acc[3][2] += a.w*b.z; acc[3][3] += a.w*b.w;
        }
    }

    const int col = n0 + tn*4;
    const bool doRope = col < ropeLim;
    const int pd2 = (col & (HD-1)) >> 1;   // pair index for (col,col+1)
    #pragma unroll
    for (int i = 0; i < 4; i++) {
        int row = m0 + tm*4 + i;
        float v0 = acc[i][0], v1 = acc[i][1], v2 = acc[i][2], v3 = acc[i][3];
        float4 o;
        if (doRope) {
            int s = row & (SEQ-1);
            const float* f = freqs + s*128 + pd2*2;   // [cos0,sin0,cos1,sin1]
            float ca = f[0], sa = f[1], cb = f[2], sb = f[3];
            o.x = v0*ca - v1*sa;  o.y = v0*sa + v1*ca;
            o.z = v2*cb - v3*sb;  o.w = v2*sb + v3*cb;
        } else {
            o.x = v0; o.y = v1; o.z = v2; o.w = v3;
        }
        *(float4*)&C[(size_t)row * ldc + col] = o;
    }
}

// ---------------------------------------------------------------------------
// Cache shift + append
// ---------------------------------------------------------------------------
__global__ __launch_bounds__(256) void cache_update(
    const float* __restrict__ cin, float* __restrict__ cout,
    const float* __restrict__ src)
{
    const int total = CACHE_ELEMS / 4;
    int i = blockIdx.x * 256 + threadIdx.x;
    if (i >= total) return;
    const int ROW4 = NKV * HD / 4;
    int b    = i / (CL * ROW4);
    int r    = i % (CL * ROW4);
    int tpos = r / ROW4;
    int c    = r % ROW4;
    float4 v;
    if (tpos < CL - SEQ) {
        v = ((const float4*)cin)[(size_t)(b * CL + tpos + SEQ) * ROW4 + c];
    } else {
        int s   = tpos - (CL - SEQ);
        int tok = b * SEQ + s;
        v = *(const float4*)(src + (size_t)tok * NQKV + c * 4);
    }
    ((float4*)cout)[i] = v;
}

// ---------------------------------------------------------------------------
// Attention, grouped + split-KV (unchanged from R3: measured 431us).
// grid = (NSPLIT, NKV, BSZ); block = 256.
// ---------------------------------------------------------------------------
__global__ __launch_bounds__(256, 2) void attn_kernel(
    const float* __restrict__ qkv, const float* __restrict__ Kc,
    const float* __restrict__ Vc, const float* __restrict__ mask,
    float* __restrict__ po, float* __restrict__ pml)
{
    extern __shared__ float smf[];
    float* q_t    = smf;                 // [128][66]
    float* s_t    = smf + 8448;          // [128][66]
    float* mask_t = smf + 16896;         // [128][18]
    float* m_s    = smf + 19200;         // [64]
    float* l_s    = smf + 19264;         // [64]
    float* sc_s   = smf + 19328;         // [64]

    const int t   = threadIdx.x;
    const int sp  = blockIdx.x;
    const int kvh = blockIdx.y;
    const int b   = blockIdx.z;

    for (int i = t; i < 64*HD; i += 256) {
        int d = i & (HD-1), q = i >> 7;
        int s = q & 15, hh = q >> 4;
        q_t[d*66 + q] = qkv[(size_t)(b*SEQ+s)*NQKV + (kvh*4+hh)*HD + d] * RSQRT_HD;
    }
    if (t < 64) { m_s[t] = -1e30f; l_s[t] = 0.f; }

    const int key0 = sp * KEYS_PER_SPLIT;
    const int hh1  = t >> 6;
    const int kk   = t & 63;
    const int dpd  = t & 127;
    const int qh   = t >> 7;
    ull acc[16] = {};

    for (int c0 = 0; c0 < KEYS_PER_SPLIT; c0 += 128) {
        for (int i = t; i < 16*128; i += 256) {
            int s = i >> 7, k = i & 127;
            mask_t[k*18 + s] = mask[s*CL + key0 + c0 + k];
        }
        __syncthreads();

        // ---- Phase 1: QK scores (pairs over q) ----
        {
            int gA = key0 + c0 + kk, gB = gA + 64;
            const float* KA = Kc + ((size_t)(b*CL + gA)*NKV + kvh)*HD;
            const float* KB = Kc + ((size_t)(b*CL + gB)*NKV + kvh)*HD;
            ull accA[8] = {}, accB[8] = {};
            #pragma unroll 4
            for (int d0 = 0; d0 < HD; d0 += 4) {
                float4 a4 = *(const float4*)(KA + d0);
                float4 b4 = *(const float4*)(KB + d0);
                #pragma unroll
                for (int dd = 0; dd < 4; dd++) {
                    float av = (&a4.x)[dd], bv = (&b4.x)[dd];
                    ull ad = pack2(av, av);
                    ull bd = pack2(bv, bv);
                    const ull* qr = (const ull*)(q_t + (d0+dd)*66 + hh1*16);
                    #pragma unroll
                    for (int i = 0; i < 8; i++) accA[i] = ffma2(ad, qr[i], accA[i]);
                    #pragma unroll
                    for (int i = 0; i < 8; i++) accB[i] = ffma2(bd, qr[i], accB[i]);
                }
            }
            #pragma unroll
            for (int i = 0; i < 8; i++) {
                ull mA = *(const ull*)(mask_t + kk*18 + 2*i);
                ull mB = *(const ull*)(mask_t + (kk+64)*18 + 2*i);
                *(ull*)(s_t + kk*66      + hh1*16 + 2*i) = addf2(accA[i], mA);
                *(ull*)(s_t + (kk+64)*66 + hh1*16 + 2*i) = addf2(accB[i], mB);
            }
        }
        __syncthreads();

        // ---- Phase 2: online softmax ----
        {
            int w = t >> 5, lane = t & 31;
            #pragma unroll
            for (int rr = 0; rr < 8; rr++) {
                int q = w*8 + rr;
                float v0 = s_t[(lane+ 0)*66 + q];
                float v1 = s_t[(lane+32)*66 + q];
                float v2 = s_t[(lane+64)*66 + q];
                float v3 = s_t[(lane+96)*66 + q];
                float mx = fmaxf(fmaxf(v0,v1), fmaxf(v2,v3));
                #pragma unroll
                for (int o = 16; o; o >>= 1) mx = fmaxf(mx, __shfl_xor_sync(0xffffffffu, mx, o));
                float mnew = fmaxf(m_s[q], mx);
                float p0 = __expf(v0 - mnew), p1 = __expf(v1 - mnew);
                float p2 = __expf(v2 - mnew), p3 = __expf(v3 - mnew);
                s_t[(lane+ 0)*66 + q] = p0;
                s_t[(lane+32)*66 + q] = p1;
                s_t[(lane+64)*66 + q] = p2;
                s_t[(lane+96)*66 + q] = p3;
                float sum = (p0+p1) + (p2+p3);
                #pragma unroll
                for (int o = 16; o; o >>= 1) sum += __shfl_xor_sync(0xffffffffu, sum, o);
                if (lane == 0) {
                    float sc = __expf(m_s[q] - mnew);
                    sc_s[q] = sc;
                    l_s[q]  = l_s[q] * sc + sum;
                    m_s[q]  = mnew;
                }
            }
        }
        __syncthreads();

        // ---- Phase 3: P @ V (pairs over q) ----
        {
            #pragma unroll
            for (int i = 0; i < 16; i++) {
                ull scp = *(const ull*)(sc_s + qh*32 + 2*i);
                acc[i] = mulf2(acc[i], scp);
            }
            const float* Vp = Vc + ((size_t)(b*CL + key0 + c0)*NKV + kvh)*HD + dpd;
            #pragma unroll 2
            for (int k = 0; k < 128; k += 2) {
                float va = Vp[(size_t)(k+0)*NKV*HD];
                float vb = Vp[(size_t)(k+1)*NKV*HD];
                ull vda = pack2(va, va);
                ull vdb = pack2(vb, vb);
                const ull* pra = (const ull*)(s_t + (k+0)*66 + qh*32);
                const ull* prb = (const ull*)(s_t + (k+1)*66 + qh*32);
                #pragma unroll
                for (int i = 0; i < 16; i++) acc[i] = ffma2(vda, pra[i], acc[i]);
                #pragma unroll
                for (int i = 0; i < 16; i++) acc[i] = ffma2(vdb, prb[i], acc[i]);
            }
        }
        __syncthreads();
    }

    size_t base = ((size_t)(b*NKV + kvh)*NSPLIT + sp)*64;
    #pragma unroll
    for (int i = 0; i < 16; i++) {
        float2 v = unpk(acc[i]);
        int q0 = qh*32 + 2*i;
        po[(base + q0  )*128 + dpd] = v.x;
        po[(base + q0+1)*128 + dpd] = v.y;
    }
    if (t < 64) {
        pml[(base + t)*2 + 0] = m_s[t];
        pml[(base + t)*2 + 1] = l_s[t];
    }
}

// ---------------------------------------------------------------------------
// Combine split-KV partials -> attn output
// ---------------------------------------------------------------------------
__global__ __launch_bounds__(256) void attn_combine(
    const float* __restrict__ po, const float* __restrict__ pml,
    float* __restrict__ attn_out)
{
    __shared__ float wsm[NSPLIT][64];
    __shared__ float linv[64];
    const int t  = threadIdx.x;
    const int bk = blockIdx.x;
    if (t < 64) {
        float mv[NSPLIT];
        float M = -1e30f;
        #pragma unroll
        for (int i = 0; i < NSPLIT; i++) {
            mv[i] = pml[((size_t)(bk*NSPLIT + i)*64 + t)*2 + 0];
            M = fmaxf(M, mv[i]);
        }
        float L = 0.f;
        #pragma unroll
        for (int i = 0; i < NSPLIT; i++) {
            float w = __expf(mv[i] - M);
            wsm[i][t] = w;
            L += w * pml[((size_t)(bk*NSPLIT + i)*64 + t)*2 + 1];
        }
        linv[t] = 1.f / L;
    }
    __syncthreads();
    const int d  = t & 127;
    const int qh = t >> 7;
    const int b = bk >> 3, kvh = bk & 7;
    for (int q = qh*32; q < qh*32 + 32; q++) {
        float o = 0.f;
        #pragma unroll
        for (int i = 0; i < NSPLIT; i++)
            o += po[((size_t)(bk*NSPLIT + i)*64 + q)*128 + d] * wsm[i][q];
        o *= linv[q];
        int s = q & 15, hh = q >> 4;
        attn_out[(size_t)(b*SEQ + s)*DIM + (kvh*4 + hh)*HD + d] = o;
    }
}

// ---------------------------------------------------------------------------
extern "C" void kernel_launch(void* const* d_in, const int* in_sizes, int n_in,
                              void* d_out, int out_size)
{
    const float* x     = (const float*)d_in[0];
    const float* mask  = (const float*)d_in[1];
    const float* freqs = (const float*)d_in[2];
    const float* ck    = (const float*)d_in[3];
    const float* cv    = (const float*)d_in[4];
    const float* wq    = (const float*)d_in[5];
    const float* wk    = (const float*)d_in[6];
    const float* wv    = (const float*)d_in[7];
    const float* wo    = (const float*)d_in[8];
    float* out = (float*)d_out;

    float *qkv, *attn, *po, *pml;
    cudaGetSymbolAddress((void**)&qkv,  g_qkv);
    cudaGetSymbolAddress((void**)&attn, g_attn);
    cudaGetSymbolAddress((void**)&po,   g_po);
    cudaGetSymbolAddress((void**)&pml,  g_pml);

    static int smem_set = 0;
    const int attn_smem = 19392 * sizeof(float);   // 77568 B
    if (!smem_set) {
        cudaFuncSetAttribute(attn_kernel, cudaFuncAttributeMaxDynamicSharedMemorySize, attn_smem);
        smem_set = 1;
    }

    // Fused QKV projection + RoPE epilogue (single launch, 192 blocks)
    gemm_tn<<<dim3(NQKV/64, 2), 256>>>(x, wq, wk, wv, qkv, NQKV, freqs, ROPE_LIM);

    // Cache shift + append
    int cb = (CACHE_ELEMS/4 + 255) / 256;
    cache_update<<<cb, 256>>>(ck, out + CK_OFF, qkv + DIM);
    cache_update<<<cb, 256>>>(cv, out + CV_OFF, qkv + DIM + NKV*HD);

    // Attention (split-KV) + combine
    attn_kernel<<<dim3(NSPLIT, NKV, BSZ), 256, attn_smem>>>(
        qkv, out + CK_OFF, out + CV_OFF, mask, po, pml);
    attn_combine<<<BSZ*NKV, 256>>>(po, pml, attn);

    // Output projection
    gemm_tn<<<dim3(DIM/64, 2), 256>>>(attn, wo, nullptr, nullptr, out, DIM, nullptr, 0);
}

// round 7
// speedup vs baseline: 2.2026x; 1.4894x over previous
#include <cuda_runtime.h>
#include <cstdint>

#define BSZ 8
#define SEQ 16
#define DIM 4096
#define NH 32
#define NKV 8
#define HD 128
#define CL 4096
#define NT (BSZ*SEQ)                 // 128 tokens
#define NQKV (DIM + 2*NKV*HD)        // 6144
#define ROPE_LIM (DIM + NKV*HD)      // 5120
#define CACHE_ELEMS (BSZ*CL*NKV*HD)
#define CK_OFF ((size_t)NT*DIM)
#define CV_OFF (CK_OFF + CACHE_ELEMS)
#define RSQRT_HD 0.08838834764831845f
#define NSPLIT 8
#define KEYS_PER_SPLIT (CL/NSPLIT)   // 512

typedef unsigned long long ull;

__device__ float g_qkv[(size_t)NT*NQKV];
__device__ float g_attn[(size_t)NT*DIM];
__device__ float g_po[(size_t)BSZ*NKV*NSPLIT*64*128];
__device__ float g_pml[(size_t)BSZ*NKV*NSPLIT*64*2];

// ---- packed f32x2 helpers (attention) -------------------------------------
__device__ __forceinline__ ull ffma2(ull a, ull b, ull c) {
    ull d; asm("fma.rn.f32x2 %0, %1, %2, %3;" : "=l"(d) : "l"(a), "l"(b), "l"(c));
    return d;
}
__device__ __forceinline__ ull addf2(ull a, ull b) {
    ull d; asm("add.rn.f32x2 %0, %1, %2;" : "=l"(d) : "l"(a), "l"(b)); return d;
}
__device__ __forceinline__ ull mulf2(ull a, ull b) {
    ull d; asm("mul.rn.f32x2 %0, %1, %2;" : "=l"(d) : "l"(a), "l"(b)); return d;
}
__device__ __forceinline__ ull pack2(float x, float y) {
    ull r; asm("mov.b64 %0, {%1, %2};" : "=l"(r) : "f"(x), "f"(y)); return r;
}
__device__ __forceinline__ float2 unpk(ull v) {
    float2 r; asm("mov.b64 {%0, %1}, %2;" : "=f"(r.x), "=f"(r.y) : "l"(v)); return r;
}

// ---- bf16 mma.sync (baseline sm_80+ ISA; compiles at compute_103) ---------
#define MMA_BF16(d, a0,a1,a2,a3, b0,b1) \
    asm volatile( \
        "mma.sync.aligned.m16n8k16.row.col.f32.bf16.bf16.f32 " \
        "{%0,%1,%2,%3}, {%4,%5,%6,%7}, {%8,%9}, {%0,%1,%2,%3};" \
        : "+f"(d[0]), "+f"(d[1]), "+f"(d[2]), "+f"(d[3]) \
        : "r"(a0), "r"(a1), "r"(a2), "r"(a3), "r"(b0), "r"(b1))

// split one float pair -> (hi bf16x2, lo bf16x2); low half = first element
__device__ __forceinline__ void split2(float x, float y, uint32_t& hi, uint32_t& lo) {
    uint32_t ux = __float_as_uint(x), uy = __float_as_uint(y);
    float hx = __uint_as_float(ux & 0xFFFF0000u);
    float hy = __uint_as_float(uy & 0xFFFF0000u);
    hi = __byte_perm(ux, uy, 0x7632);
    lo = __byte_perm(__float_as_uint(x - hx), __float_as_uint(y - hy), 0x7632);
}

// ---------------------------------------------------------------------------
// Tensor-core GEMM (mma.sync bf16, split hi+lo): C[m][n] = sum_k A[m][k]*W[n][k]
// M=128 (all tokens), BN=64/block, BK=64/stage. 8 warps, each a 32x32 tile.
// 3 HMMA products per k16: Ah*Wh + Ah*Wl + Al*Wh. Optional RoPE epilogue.
// ---------------------------------------------------------------------------
#define BKS 64
#define NSTG (DIM/BKS)          // 64
#define ASTR 72                 // bf16 elements per row (bank-conflict-free)
#define U16_AHI 0
#define U16_ALO (128*ASTR)           // 9216
#define U16_WHI (2*128*ASTR)         // 18432
#define U16_WLO (2*128*ASTR + 64*ASTR)
#define GEMM_SMEM ((2*128*ASTR + 2*64*ASTR) * 2)   // 55296 bytes

__global__ __launch_bounds__(256) void gemm_mma(
    const float* __restrict__ A,
    const float* __restrict__ W0, const float* __restrict__ W1,
    const float* __restrict__ W2,
    float* __restrict__ C, int ldc,
    const float* __restrict__ freqs, int ropeLim)
{
    extern __shared__ char smraw[];
    uint16_t* sm16 = (uint16_t*)smraw;

    const int t    = threadIdx.x;
    const int wid  = t >> 5;
    const int lane = t & 31;
    const int g    = lane >> 2;     // fragment group row/col
    const int tg   = lane & 3;      // thread-in-group
    const int wm   = wid >> 1;      // warp m tile (0..3) * 32
    const int wn   = wid & 1;       // warp n tile (0..1) * 32
    const int n0   = blockIdx.x * 64;

    const float* W = W0; int nr = n0;
    if (W1 != nullptr && n0 >= DIM) {
        if (n0 < DIM + NKV*HD) { W = W1; nr = n0 - DIM; }
        else                   { W = W2; nr = n0 - DIM - NKV*HD; }
    }

    float acc[2][4][4] = {};
    float4 pa[8], pw[4];

    // prefetch stage 0
    #pragma unroll
    for (int it = 0; it < 8; it++) {
        int v = t + it*256, row = v >> 4, gq = v & 15;
        pa[it] = *(const float4*)(A + (size_t)row * DIM + gq*4);
    }
    #pragma unroll
    for (int it = 0; it < 4; it++) {
        int v = t + it*256, row = v >> 4, gq = v & 15;
        pw[it] = *(const float4*)(W + (size_t)(nr + row) * DIM + gq*4);
    }

    for (int st = 0; st < NSTG; st++) {
        __syncthreads();   // previous compute done
        // convert + store stage tiles
        #pragma unroll
        for (int it = 0; it < 8; it++) {
            int v = t + it*256, row = v >> 4, gq = v & 15;
            int idx = row*ASTR + gq*4;
            uint32_t h0, l0, h1, l1;
            split2(pa[it].x, pa[it].y, h0, l0);
            split2(pa[it].z, pa[it].w, h1, l1);
            *(uint32_t*)&sm16[U16_AHI + idx]     = h0;
            *(uint32_t*)&sm16[U16_AHI + idx + 2] = h1;
            *(uint32_t*)&sm16[U16_ALO + idx]     = l0;
            *(uint32_t*)&sm16[U16_ALO + idx + 2] = l1;
        }
        #pragma unroll
        for (int it = 0; it < 4; it++) {
            int v = t + it*256, row = v >> 4, gq = v & 15;
            int idx = row*ASTR + gq*4;
            uint32_t h0, l0, h1, l1;
            split2(pw[it].x, pw[it].y, h0, l0);
            split2(pw[it].z, pw[it].w, h1, l1);
            *(uint32_t*)&sm16[U16_WHI + idx]     = h0;
            *(uint32_t*)&sm16[U16_WHI + idx + 2] = h1;
            *(uint32_t*)&sm16[U16_WLO + idx]     = l0;
            *(uint32_t*)&sm16[U16_WLO + idx + 2] = l1;
        }
        __syncthreads();

        // prefetch next stage (overlaps with MMA below)
        if (st + 1 < NSTG) {
            const int k0 = (st + 1) * BKS;
            #pragma unroll
            for (int it = 0; it < 8; it++) {
                int v = t + it*256, row = v >> 4, gq = v & 15;
                pa[it] = *(const float4*)(A + (size_t)row * DIM + k0 + gq*4);
            }
            #pragma unroll
            for (int it = 0; it < 4; it++) {
                int v = t + it*256, row = v >> 4, gq = v & 15;
                pw[it] = *(const float4*)(W + (size_t)(nr + row) * DIM + k0 + gq*4);
            }
        }

        // ---- MMA over 4 k16 steps ----
        #pragma unroll
        for (int kk = 0; kk < 4; kk++) {
            const int kb = kk*16 + 2*tg;
            uint32_t bh0[4], bh1[4], bl0[4], bl1[4];
            #pragma unroll
            for (int nt = 0; nt < 4; nt++) {
                int bi = (wn*32 + nt*8 + g)*ASTR + kb;
                bh0[nt] = *(const uint32_t*)&sm16[U16_WHI + bi];
                bh1[nt] = *(const uint32_t*)&sm16[U16_WHI + bi + 8];
                bl0[nt] = *(const uint32_t*)&sm16[U16_WLO + bi];
                bl1[nt] = *(const uint32_t*)&sm16[U16_WLO + bi + 8];
            }
            #pragma unroll
            for (int mh = 0; mh < 2; mh++) {
                int ai = (wm*32 + mh*16 + g)*ASTR + kb;
                uint32_t ah0 = *(const uint32_t*)&sm16[U16_AHI + ai];
                uint32_t ah1 = *(const uint32_t*)&sm16[U16_AHI + ai + 8*ASTR];
                uint32_t ah2 = *(const uint32_t*)&sm16[U16_AHI + ai + 8];
                uint32_t ah3 = *(const uint32_t*)&sm16[U16_AHI + ai + 8*ASTR + 8];
                uint32_t al0 = *(const uint32_t*)&sm16[U16_ALO + ai];
                uint32_t al1 = *(const uint32_t*)&sm16[U16_ALO + ai + 8*ASTR];
                uint32_t al2 = *(const uint32_t*)&sm16[U16_ALO + ai + 8];
                uint32_t al3 = *(const uint32_t*)&sm16[U16_ALO + ai + 8*ASTR + 8];
                #pragma unroll
                for (int nt = 0; nt < 4; nt++) {
                    MMA_BF16(acc[mh][nt], ah0, ah1, ah2, ah3, bh0[nt], bh1[nt]);
                    MMA_BF16(acc[mh][nt], ah0, ah1, ah2, ah3, bl0[nt], bl1[nt]);
                    MMA_BF16(acc[mh][nt], al0, al1, al2, al3, bh0[nt], bh1[nt]);
                }
            }
        }
    }

    // ---- epilogue (+ optional RoPE; fragment cols are adjacent pairs) ----
    const bool doRope = n0 < ropeLim;
    #pragma unroll
    for (int mh = 0; mh < 2; mh++) {
        #pragma unroll
        for (int nt = 0; nt < 4; nt++) {
            int r0 = wm*32 + mh*16 + g;
            int r1 = r0 + 8;
            int gc = n0 + wn*32 + nt*8 + 2*tg;
            float v0 = acc[mh][nt][0], v1 = acc[mh][nt][1];
            float v2 = acc[mh][nt][2], v3 = acc[mh][nt][3];
            float2 o0, o1;
            if (doRope) {
                int pd2 = (gc & (HD-1)) >> 1;
                const float* f0 = freqs + (r0 & (SEQ-1))*128 + pd2*2;
                const float* f1 = freqs + (r1 & (SEQ-1))*128 + pd2*2;
                float ca0 = f0[0], sa0 = f0[1];
                float ca1 = f1[0], sa1 = f1[1];
                o0.x = v0*ca0 - v1*sa0;  o0.y = v0*sa0 + v1*ca0;
                o1.x = v2*ca1 - v3*sa1;  o1.y = v2*sa1 + v3*ca1;
            } else {
                o0.x = v0; o0.y = v1; o1.x = v2; o1.y = v3;
            }
            *(float2*)&C[(size_t)r0 * ldc + gc] = o0;
            *(float2*)&C[(size_t)r1 * ldc + gc] = o1;
        }
    }
}

// ---------------------------------------------------------------------------
// Cache shift + append
// ---------------------------------------------------------------------------
__global__ __launch_bounds__(256) void cache_update(
    const float* __restrict__ cin, float* __restrict__ cout,
    const float* __restrict__ src)
{
    const int total = CACHE_ELEMS / 4;
    int i = blockIdx.x * 256 + threadIdx.x;
    if (i >= total) return;
    const int ROW4 = NKV * HD / 4;
    int b    = i / (CL * ROW4);
    int r    = i % (CL * ROW4);
    int tpos = r / ROW4;
    int c    = r % ROW4;
    float4 v;
    if (tpos < CL - SEQ) {
        v = ((const float4*)cin)[(size_t)(b * CL + tpos + SEQ) * ROW4 + c];
    } else {
        int s   = tpos - (CL - SEQ);
        int tok = b * SEQ + s;
        v = *(const float4*)(src + (size_t)tok * NQKV + c * 4);
    }
    ((float4*)cout)[i] = v;
}

// ---------------------------------------------------------------------------
// Attention, grouped + split-KV (unchanged; measured 432us)
// ---------------------------------------------------------------------------
__global__ __launch_bounds__(256, 2) void attn_kernel(
    const float* __restrict__ qkv, const float* __restrict__ Kc,
    const float* __restrict__ Vc, const float* __restrict__ mask,
    float* __restrict__ po, float* __restrict__ pml)
{
    extern __shared__ float smf[];
    float* q_t    = smf;                 // [128][66]
    float* s_t    = smf + 8448;          // [128][66]
    float* mask_t = smf + 16896;         // [128][18]
    float* m_s    = smf + 19200;
    float* l_s    = smf + 19264;
    float* sc_s   = smf + 19328;

    const int t   = threadIdx.x;
    const int sp  = blockIdx.x;
    const int kvh = blockIdx.y;
    const int b   = blockIdx.z;

    for (int i = t; i < 64*HD; i += 256) {
        int d = i & (HD-1), q = i >> 7;
        int s = q & 15, hh = q >> 4;
        q_t[d*66 + q] = qkv[(size_t)(b*SEQ+s)*NQKV + (kvh*4+hh)*HD + d] * RSQRT_HD;
    }
    if (t < 64) { m_s[t] = -1e30f; l_s[t] = 0.f; }

    const int key0 = sp * KEYS_PER_SPLIT;
    const int hh1  = t >> 6;
    const int kk   = t & 63;
    const int dpd  = t & 127;
    const int qh   = t >> 7;
    ull acc[16] = {};

    for (int c0 = 0; c0 < KEYS_PER_SPLIT; c0 += 128) {
        for (int i = t; i < 16*128; i += 256) {
            int s = i >> 7, k = i & 127;
            mask_t[k*18 + s] = mask[s*CL + key0 + c0 + k];
        }
        __syncthreads();

        {
            int gA = key0 + c0 + kk, gB = gA + 64;
            const float* KA = Kc + ((size_t)(b*CL + gA)*NKV + kvh)*HD;
            const float* KB = Kc + ((size_t)(b*CL + gB)*NKV + kvh)*HD;
            ull accA[8] = {}, accB[8] = {};
            #pragma unroll 4
            for (int d0 = 0; d0 < HD; d0 += 4) {
                float4 a4 = *(const float4*)(KA + d0);
                float4 b4 = *(const float4*)(KB + d0);
                #pragma unroll
                for (int dd = 0; dd < 4; dd++) {
                    float av = (&a4.x)[dd], bv = (&b4.x)[dd];
                    ull ad = pack2(av, av);
                    ull bd = pack2(bv, bv);
                    const ull* qr = (const ull*)(q_t + (d0+dd)*66 + hh1*16);
                    #pragma unroll
                    for (int i = 0; i < 8; i++) accA[i] = ffma2(ad, qr[i], accA[i]);
                    #pragma unroll
                    for (int i = 0; i < 8; i++) accB[i] = ffma2(bd, qr[i], accB[i]);
                }
            }
            #pragma unroll
            for (int i = 0; i < 8; i++) {
                ull mA = *(const ull*)(mask_t + kk*18 + 2*i);
                ull mB = *(const ull*)(mask_t + (kk+64)*18 + 2*i);
                *(ull*)(s_t + kk*66      + hh1*16 + 2*i) = addf2(accA[i], mA);
                *(ull*)(s_t + (kk+64)*66 + hh1*16 + 2*i) = addf2(accB[i], mB);
            }
        }
        __syncthreads();

        {
            int w = t >> 5, lane = t & 31;
            #pragma unroll
            for (int rr = 0; rr < 8; rr++) {
                int q = w*8 + rr;
                float v0 = s_t[(lane+ 0)*66 + q];
                float v1 = s_t[(lane+32)*66 + q];
                float v2 = s_t[(lane+64)*66 + q];
                float v3 = s_t[(lane+96)*66 + q];
                float mx = fmaxf(fmaxf(v0,v1), fmaxf(v2,v3));
                #pragma unroll
                for (int o = 16; o; o >>= 1) mx = fmaxf(mx, __shfl_xor_sync(0xffffffffu, mx, o));
                float mnew = fmaxf(m_s[q], mx);
                float p0 = __expf(v0 - mnew), p1 = __expf(v1 - mnew);
                float p2 = __expf(v2 - mnew), p3 = __expf(v3 - mnew);
                s_t[(lane+ 0)*66 + q] = p0;
                s_t[(lane+32)*66 + q] = p1;
                s_t[(lane+64)*66 + q] = p2;
                s_t[(lane+96)*66 + q] = p3;
                float sum = (p0+p1) + (p2+p3);
                #pragma unroll
                for (int o = 16; o; o >>= 1) sum += __shfl_xor_sync(0xffffffffu, sum, o);
                if (lane == 0) {
                    float sc = __expf(m_s[q] - mnew);
                    sc_s[q] = sc;
                    l_s[q]  = l_s[q] * sc + sum;
                    m_s[q]  = mnew;
                }
            }
        }
        __syncthreads();

        {
            #pragma unroll
            for (int i = 0; i < 16; i++) {
                ull scp = *(const ull*)(sc_s + qh*32 + 2*i);
                acc[i] = mulf2(acc[i], scp);
            }
            const float* Vp = Vc + ((size_t)(b*CL + key0 + c0)*NKV + kvh)*HD + dpd;
            #pragma unroll 2
            for (int k = 0; k < 128; k += 2) {
                float va = Vp[(size_t)(k+0)*NKV*HD];
                float vb = Vp[(size_t)(k+1)*NKV*HD];
                ull vda = pack2(va, va);
                ull vdb = pack2(vb, vb);
                const ull* pra = (const ull*)(s_t + (k+0)*66 + qh*32);
                const ull* prb = (const ull*)(s_t + (k+1)*66 + qh*32);
                #pragma unroll
                for (int i = 0; i < 16; i++) acc[i] = ffma2(vda, pra[i], acc[i]);
                #pragma unroll
                for (int i = 0; i < 16; i++) acc[i] = ffma2(vdb, prb[i], acc[i]);
            }
        }
        __syncthreads();
    }

    size_t base = ((size_t)(b*NKV + kvh)*NSPLIT + sp)*64;
    #pragma unroll
    for (int i = 0; i < 16; i++) {
        float2 v = unpk(acc[i]);
        int q0 = qh*32 + 2*i;
        po[(base + q0  )*128 + dpd] = v.x;
        po[(base + q0+1)*128 + dpd] = v.y;
    }
    if (t < 64) {
        pml[(base + t)*2 + 0] = m_s[t];
        pml[(base + t)*2 + 1] = l_s[t];
    }
}

// ---------------------------------------------------------------------------
// Combine split-KV partials -> attn output
// ---------------------------------------------------------------------------
__global__ __launch_bounds__(256) void attn_combine(
    const float* __restrict__ po, const float* __restrict__ pml,
    float* __restrict__ attn_out)
{
    __shared__ float wsm[NSPLIT][64];
    __shared__ float linv[64];
    const int t  = threadIdx.x;
    const int bk = blockIdx.x;
    if (t < 64) {
        float mv[NSPLIT];
        float M = -1e30f;
        #pragma unroll
        for (int i = 0; i < NSPLIT; i++) {
            mv[i] = pml[((size_t)(bk*NSPLIT + i)*64 + t)*2 + 0];
            M = fmaxf(M, mv[i]);
        }
        float L = 0.f;
        #pragma unroll
        for (int i = 0; i < NSPLIT; i++) {
            float w = __expf(mv[i] - M);
            wsm[i][t] = w;
            L += w * pml[((size_t)(bk*NSPLIT + i)*64 + t)*2 + 1];
        }
        linv[t] = 1.f / L;
    }
    __syncthreads();
    const int d  = t & 127;
    const int qh = t >> 7;
    const int b = bk >> 3, kvh = bk & 7;
    for (int q = qh*32; q < qh*32 + 32; q++) {
        float o = 0.f;
        #pragma unroll
        for (int i = 0; i < NSPLIT; i++)
            o += po[((size_t)(bk*NSPLIT + i)*64 + q)*128 + d] * wsm[i][q];
        o *= linv[q];
        int s = q & 15, hh = q >> 4;
        attn_out[(size_t)(b*SEQ + s)*DIM + (kvh*4 + hh)*HD + d] = o;
    }
}

// ---------------------------------------------------------------------------
extern "C" void kernel_launch(void* const* d_in, const int* in_sizes, int n_in,
                              void* d_out, int out_size)
{
    const float* x     = (const float*)d_in[0];
    const float* mask  = (const float*)d_in[1];
    const float* freqs = (const float*)d_in[2];
    const float* ck    = (const float*)d_in[3];
    const float* cv    = (const float*)d_in[4];
    const float* wq    = (const float*)d_in[5];
    const float* wk    = (const float*)d_in[6];
    const float* wv    = (const float*)d_in[7];
    const float* wo    = (const float*)d_in[8];
    float* out = (float*)d_out;

    float *qkv, *attn, *po, *pml;
    cudaGetSymbolAddress((void**)&qkv,  g_qkv);
    cudaGetSymbolAddress((void**)&attn, g_attn);
    cudaGetSymbolAddress((void**)&po,   g_po);
    cudaGetSymbolAddress((void**)&pml,  g_pml);

    static int smem_set = 0;
    const int attn_smem = 19392 * sizeof(float);   // 77568 B
    if (!smem_set) {
        cudaFuncSetAttribute(attn_kernel, cudaFuncAttributeMaxDynamicSharedMemorySize, attn_smem);
        cudaFuncSetAttribute(gemm_mma, cudaFuncAttributeMaxDynamicSharedMemorySize, GEMM_SMEM);
        smem_set = 1;
    }

    // Fused QKV projection (bf16 mma.sync, split hi+lo) + RoPE epilogue
    gemm_mma<<<NQKV/64, 256, GEMM_SMEM>>>(x, wq, wk, wv, qkv, NQKV, freqs, ROPE_LIM);

    // Cache shift + append
    int cb = (CACHE_ELEMS/4 + 255) / 256;
    cache_update<<<cb, 256>>>(ck, out + CK_OFF, qkv + DIM);
    cache_update<<<cb, 256>>>(cv, out + CV_OFF, qkv + DIM + NKV*HD);

    // Attention (split-KV) + combine
    attn_kernel<<<dim3(NSPLIT, NKV, BSZ), 256, attn_smem>>>(
        qkv, out + CK_OFF, out + CV_OFF, mask, po, pml);
    attn_combine<<<BSZ*NKV, 256>>>(po, pml, attn);

    // Output projection (bf16 mma.sync)
    gemm_mma<<<DIM/64, 256, GEMM_SMEM>>>(attn, wo, nullptr, nullptr, out, DIM, nullptr, 0);
}

// round 8
// speedup vs baseline: 3.1993x; 1.4525x over previous
#include <cuda_runtime.h>
#include <cstdint>

#define BSZ 8
#define SEQ 16
#define DIM 4096
#define NH 32
#define NKV 8
#define HD 128
#define CL 4096
#define NT (BSZ*SEQ)                 // 128 tokens
#define NQKV (DIM + 2*NKV*HD)        // 6144
#define ROPE_LIM (DIM + NKV*HD)      // 5120
#define CACHE_ELEMS (BSZ*CL*NKV*HD)
#define CK_OFF ((size_t)NT*DIM)
#define CV_OFF (CK_OFF + CACHE_ELEMS)
#define RSQRT_HD 0.08838834764831845f
#define NSPLIT 8
#define KEYS_PER_SPLIT (CL/NSPLIT)   // 512

typedef unsigned long long ull;

__device__ float g_qkv[(size_t)NT*NQKV];
__device__ float g_attn[(size_t)NT*DIM];
__device__ float g_po[(size_t)BSZ*NKV*NSPLIT*64*128];
__device__ float g_pml[(size_t)BSZ*NKV*NSPLIT*64*2];

// ---- bf16 mma.sync (baseline sm_80+ ISA) ----------------------------------
#define MMA_BF16(d, a0,a1,a2,a3, b0,b1) \
    asm volatile( \
        "mma.sync.aligned.m16n8k16.row.col.f32.bf16.bf16.f32 " \
        "{%0,%1,%2,%3}, {%4,%5,%6,%7}, {%8,%9}, {%0,%1,%2,%3};" \
        : "+f"(d[0]), "+f"(d[1]), "+f"(d[2]), "+f"(d[3]) \
        : "r"(a0), "r"(a1), "r"(a2), "r"(a3), "r"(b0), "r"(b1))

__device__ __forceinline__ void ldmx4t(uint32_t& r0, uint32_t& r1,
                                       uint32_t& r2, uint32_t& r3, uint32_t addr) {
    asm volatile("ldmatrix.sync.aligned.m8n8.x4.trans.shared.b16 {%0,%1,%2,%3}, [%4];"
        : "=r"(r0), "=r"(r1), "=r"(r2), "=r"(r3) : "r"(addr));
}
__device__ __forceinline__ uint32_t smem_u32(const void* p) {
    uint32_t a;
    asm("{ .reg .u64 t; cvta.to.shared.u64 t, %1; cvt.u32.u64 %0, t; }"
        : "=r"(a) : "l"(p));
    return a;
}

// split one float pair -> (hi bf16x2, lo bf16x2); first element in low half
__device__ __forceinline__ void split2(float x, float y, uint32_t& hi, uint32_t& lo) {
    uint32_t ux = __float_as_uint(x), uy = __float_as_uint(y);
    float hx = __uint_as_float(ux & 0xFFFF0000u);
    float hy = __uint_as_float(uy & 0xFFFF0000u);
    hi = __byte_perm(ux, uy, 0x7632);
    lo = __byte_perm(__float_as_uint(x - hx), __float_as_uint(y - hy), 0x7632);
}

// ---------------------------------------------------------------------------
// Tensor-core GEMM (unchanged from R7 — measured good)
// ---------------------------------------------------------------------------
#define BKS 64
#define NSTG (DIM/BKS)          // 64
#define ASTR 72
#define U16_AHI 0
#define U16_ALO (128*ASTR)
#define U16_WHI (2*128*ASTR)
#define U16_WLO (2*128*ASTR + 64*ASTR)
#define GEMM_SMEM ((2*128*ASTR + 2*64*ASTR) * 2)   // 55296 bytes

__global__ __launch_bounds__(256) void gemm_mma(
    const float* __restrict__ A,
    const float* __restrict__ W0, const float* __restrict__ W1,
    const float* __restrict__ W2,
    float* __restrict__ C, int ldc,
    const float* __restrict__ freqs, int ropeLim)
{
    extern __shared__ char smraw[];
    uint16_t* sm16 = (uint16_t*)smraw;

    const int t    = threadIdx.x;
    const int wid  = t >> 5;
    const int lane = t & 31;
    const int g    = lane >> 2;
    const int tg   = lane & 3;
    const int wm   = wid >> 1;
    const int wn   = wid & 1;
    const int n0   = blockIdx.x * 64;

    const float* W = W0; int nr = n0;
    if (W1 != nullptr && n0 >= DIM) {
        if (n0 < DIM + NKV*HD) { W = W1; nr = n0 - DIM; }
        else                   { W = W2; nr = n0 - DIM - NKV*HD; }
    }

    float acc[2][4][4] = {};
    float4 pa[8], pw[4];

    #pragma unroll
    for (int it = 0; it < 8; it++) {
        int v = t + it*256, row = v >> 4, gq = v & 15;
        pa[it] = *(const float4*)(A + (size_t)row * DIM + gq*4);
    }
    #pragma unroll
    for (int it = 0; it < 4; it++) {
        int v = t + it*256, row = v >> 4, gq = v & 15;
        pw[it] = *(const float4*)(W + (size_t)(nr + row) * DIM + gq*4);
    }

    for (int st = 0; st < NSTG; st++) {
        __syncthreads();
        #pragma unroll
        for (int it = 0; it < 8; it++) {
            int v = t + it*256, row = v >> 4, gq = v & 15;
            int idx = row*ASTR + gq*4;
            uint32_t h0, l0, h1, l1;
            split2(pa[it].x, pa[it].y, h0, l0);
            split2(pa[it].z, pa[it].w, h1, l1);
            *(uint32_t*)&sm16[U16_AHI + idx]     = h0;
            *(uint32_t*)&sm16[U16_AHI + idx + 2] = h1;
            *(uint32_t*)&sm16[U16_ALO + idx]     = l0;
            *(uint32_t*)&sm16[U16_ALO + idx + 2] = l1;
        }
        #pragma unroll
        for (int it = 0; it < 4; it++) {
            int v = t + it*256, row = v >> 4, gq = v & 15;
            int idx = row*ASTR + gq*4;
            uint32_t h0, l0, h1, l1;
            split2(pw[it].x, pw[it].y, h0, l0);
            split2(pw[it].z, pw[it].w, h1, l1);
            *(uint32_t*)&sm16[U16_WHI + idx]     = h0;
            *(uint32_t*)&sm16[U16_WHI + idx + 2] = h1;
            *(uint32_t*)&sm16[U16_WLO + idx]     = l0;
            *(uint32_t*)&sm16[U16_WLO + idx + 2] = l1;
        }
        __syncthreads();

        if (st + 1 < NSTG) {
            const int k0 = (st + 1) * BKS;
            #pragma unroll
            for (int it = 0; it < 8; it++) {
                int v = t + it*256, row = v >> 4, gq = v & 15;
                pa[it] = *(const float4*)(A + (size_t)row * DIM + k0 + gq*4);
            }
            #pragma unroll
            for (int it = 0; it < 4; it++) {
                int v = t + it*256, row = v >> 4, gq = v & 15;
                pw[it] = *(const float4*)(W + (size_t)(nr + row) * DIM + k0 + gq*4);
            }
        }

        #pragma unroll
        for (int kk = 0; kk < 4; kk++) {
            const int kb = kk*16 + 2*tg;
            uint32_t bh0[4], bh1[4], bl0[4], bl1[4];
            #pragma unroll
            for (int nt = 0; nt < 4; nt++) {
                int bi = (wn*32 + nt*8 + g)*ASTR + kb;
                bh0[nt] = *(const uint32_t*)&sm16[U16_WHI + bi];
                bh1[nt] = *(const uint32_t*)&sm16[U16_WHI + bi + 8];
                bl0[nt] = *(const uint32_t*)&sm16[U16_WLO + bi];
                bl1[nt] = *(const uint32_t*)&sm16[U16_WLO + bi + 8];
            }
            #pragma unroll
            for (int mh = 0; mh < 2; mh++) {
                int ai = (wm*32 + mh*16 + g)*ASTR + kb;
                uint32_t ah0 = *(const uint32_t*)&sm16[U16_AHI + ai];
                uint32_t ah1 = *(const uint32_t*)&sm16[U16_AHI + ai + 8*ASTR];
                uint32_t ah2 = *(const uint32_t*)&sm16[U16_AHI + ai + 8];
                uint32_t ah3 = *(const uint32_t*)&sm16[U16_AHI + ai + 8*ASTR + 8];
                uint32_t al0 = *(const uint32_t*)&sm16[U16_ALO + ai];
                uint32_t al1 = *(const uint32_t*)&sm16[U16_ALO + ai + 8*ASTR];
                uint32_t al2 = *(const uint32_t*)&sm16[U16_ALO + ai + 8];
                uint32_t al3 = *(const uint32_t*)&sm16[U16_ALO + ai + 8*ASTR + 8];
                #pragma unroll
                for (int nt = 0; nt < 4; nt++) {
                    MMA_BF16(acc[mh][nt], ah0, ah1, ah2, ah3, bh0[nt], bh1[nt]);
                    MMA_BF16(acc[mh][nt], ah0, ah1, ah2, ah3, bl0[nt], bl1[nt]);
                    MMA_BF16(acc[mh][nt], al0, al1, al2, al3, bh0[nt], bh1[nt]);
                }
            }
        }
    }

    const bool doRope = n0 < ropeLim;
    #pragma unroll
    for (int mh = 0; mh < 2; mh++) {
        #pragma unroll
        for (int nt = 0; nt < 4; nt++) {
            int r0 = wm*32 + mh*16 + g;
            int r1 = r0 + 8;
            int gc = n0 + wn*32 + nt*8 + 2*tg;
            float v0 = acc[mh][nt][0], v1 = acc[mh][nt][1];
            float v2 = acc[mh][nt][2], v3 = acc[mh][nt][3];
            float2 o0, o1;
            if (doRope) {
                int pd2 = (gc & (HD-1)) >> 1;
                const float* f0 = freqs + (r0 & (SEQ-1))*128 + pd2*2;
                const float* f1 = freqs + (r1 & (SEQ-1))*128 + pd2*2;
                float ca0 = f0[0], sa0 = f0[1];
                float ca1 = f1[0], sa1 = f1[1];
                o0.x = v0*ca0 - v1*sa0;  o0.y = v0*sa0 + v1*ca0;
                o1.x = v2*ca1 - v3*sa1;  o1.y = v2*sa1 + v3*ca1;
            } else {
                o0.x = v0; o0.y = v1; o1.x = v2; o1.y = v3;
            }
            *(float2*)&C[(size_t)r0 * ldc + gc] = o0;
            *(float2*)&C[(size_t)r1 * ldc + gc] = o1;
        }
    }
}

// ---------------------------------------------------------------------------
// Cache shift + append
// ---------------------------------------------------------------------------
__global__ __launch_bounds__(256) void cache_update(
    const float* __restrict__ cin, float* __restrict__ cout,
    const float* __restrict__ src)
{
    const int total = CACHE_ELEMS / 4;
    int i = blockIdx.x * 256 + threadIdx.x;
    if (i >= total) return;
    const int ROW4 = NKV * HD / 4;
    int b    = i / (CL * ROW4);
    int r    = i % (CL * ROW4);
    int tpos = r / ROW4;
    int c    = r % ROW4;
    float4 v;
    if (tpos < CL - SEQ) {
        v = ((const float4*)cin)[(size_t)(b * CL + tpos + SEQ) * ROW4 + c];
    } else {
        int s   = tpos - (CL - SEQ);
        int tok = b * SEQ + s;
        v = *(const float4*)(src + (size_t)tok * NQKV + c * 4);
    }
    ((float4*)cout)[i] = v;
}

// ---------------------------------------------------------------------------
// Attention via mma.sync split-bf16. grid (NSPLIT, NKV, BSZ), 256 threads.
// 64 q (4 heads x 16 seq) over 512 keys, 64-key chunks.
// ---------------------------------------------------------------------------
#define AST 136     // u16 stride for 128-wide tiles (q, K, V)
#define PST 72      // u16 stride for P (64 keys)
#define CHK 64

#define O_QHI 0
#define O_QLO (O_QHI + 17408)
#define O_KHI (O_QLO + 17408)
#define O_KLO (O_KHI + 17408)
#define O_VHI (O_KLO + 17408)
#define O_VLO (O_VHI + 17408)
#define O_ST  (O_VLO + 17408)     // f32 [64][68]
#define O_PHI (O_ST  + 17408)     // u16 [64][72]
#define O_PLO (O_PHI + 9216)
#define O_MSK (O_PLO + 9216)      // f32 [16][66]
#define O_MS  (O_MSK + 4224)
#define O_LS  (O_MS  + 256)
#define O_SCS (O_LS  + 256)
#define ATTN_SMEM (O_SCS + 256)   // 145280 bytes

__global__ __launch_bounds__(256) void attn_mma(
    const float* __restrict__ qkv, const float* __restrict__ Kc,
    const float* __restrict__ Vc, const float* __restrict__ mask,
    float* __restrict__ po, float* __restrict__ pml)
{
    extern __shared__ char sm[];
    uint16_t* qhi = (uint16_t*)(sm + O_QHI);
    uint16_t* qlo = (uint16_t*)(sm + O_QLO);
    uint16_t* khi = (uint16_t*)(sm + O_KHI);
    uint16_t* klo = (uint16_t*)(sm + O_KLO);
    uint16_t* vhi = (uint16_t*)(sm + O_VHI);
    uint16_t* vlo = (uint16_t*)(sm + O_VLO);
    float*    s_t = (float*)(sm + O_ST);
    uint16_t* phi = (uint16_t*)(sm + O_PHI);
    uint16_t* plo = (uint16_t*)(sm + O_PLO);
    float*    msk = (float*)(sm + O_MSK);
    float*    m_s = (float*)(sm + O_MS);
    float*    l_s = (float*)(sm + O_LS);
    float*    sc_s= (float*)(sm + O_SCS);
    const uint32_t smb = smem_u32(sm);

    const int t    = threadIdx.x;
    const int wid  = t >> 5;
    const int lane = t & 31;
    const int g    = lane >> 2;
    const int tg   = lane & 3;
    const int wm   = wid >> 1;           // 0..3 -> m0 = wm*16
    const int wn   = wid & 1;
    const int m0   = wm * 16;
    const int sp   = blockIdx.x;
    const int kvh  = blockIdx.y;
    const int b    = blockIdx.z;
    const int key0 = sp * KEYS_PER_SPLIT;

    // ---- q load + scale + split (once per block) ----
    #pragma unroll
    for (int it = 0; it < 8; it++) {
        int idx = t + it*256;          // 2048 float4
        int q = idx >> 5, dq = idx & 31;
        const float* src = qkv + (size_t)(b*SEQ + (q & 15))*NQKV
                           + (kvh*4 + (q >> 4))*HD + dq*4;
        float4 v = *(const float4*)src;
        v.x *= RSQRT_HD; v.y *= RSQRT_HD; v.z *= RSQRT_HD; v.w *= RSQRT_HD;
        uint32_t h0, l0, h1, l1;
        split2(v.x, v.y, h0, l0);
        split2(v.z, v.w, h1, l1);
        int o = q*AST + dq*4;
        *(uint32_t*)&qhi[o] = h0;   *(uint32_t*)&qhi[o+2] = h1;
        *(uint32_t*)&qlo[o] = l0;   *(uint32_t*)&qlo[o+2] = l1;
    }
    if (t < 64) { m_s[t] = -1e30f; l_s[t] = 0.f; }

    float accO[8][4] = {};

    for (int c0 = 0; c0 < KEYS_PER_SPLIT; c0 += CHK) {
        // ---- K, V chunk conversion ----
        #pragma unroll
        for (int it = 0; it < 8; it++) {
            int idx = t + it*256;
            int key = idx >> 5, dq = idx & 31;
            size_t gofs = ((size_t)(b*CL + key0 + c0 + key)*NKV + kvh)*HD + dq*4;
            float4 kv = *(const float4*)(Kc + gofs);
            float4 vv = *(const float4*)(Vc + gofs);
            uint32_t h0, l0, h1, l1;
            int o = key*AST + dq*4;
            split2(kv.x, kv.y, h0, l0); split2(kv.z, kv.w, h1, l1);
            *(uint32_t*)&khi[o] = h0;  *(uint32_t*)&khi[o+2] = h1;
            *(uint32_t*)&klo[o] = l0;  *(uint32_t*)&klo[o+2] = l1;
            split2(vv.x, vv.y, h0, l0); split2(vv.z, vv.w, h1, l1);
            *(uint32_t*)&vhi[o] = h0;  *(uint32_t*)&vhi[o+2] = h1;
            *(uint32_t*)&vlo[o] = l0;  *(uint32_t*)&vlo[o+2] = l1;
        }
        // mask chunk [16][64]
        #pragma unroll
        for (int j = 0; j < 4; j++) {
            int i = t + j*256;
            int s = i >> 6, k = i & 63;
            msk[s*66 + k] = mask[(size_t)s*CL + key0 + c0 + k];
        }
        __syncthreads();

        // ---- QK: scores[64q][64keys], 3 products, K=128 (8 k16 steps) ----
        {
            float acc[4][4] = {};
            #pragma unroll
            for (int kk = 0; kk < 8; kk++) {
                const int kb = kk*16 + 2*tg;
                int ai = (m0 + g)*AST + kb;
                uint32_t ah0 = *(const uint32_t*)&qhi[ai];
                uint32_t ah1 = *(const uint32_t*)&qhi[ai + 8*AST];
                uint32_t ah2 = *(const uint32_t*)&qhi[ai + 8];
                uint32_t ah3 = *(const uint32_t*)&qhi[ai + 8*AST + 8];
                uint32_t al0 = *(const uint32_t*)&qlo[ai];
                uint32_t al1 = *(const uint32_t*)&qlo[ai + 8*AST];
                uint32_t al2 = *(const uint32_t*)&qlo[ai + 8];
                uint32_t al3 = *(const uint32_t*)&qlo[ai + 8*AST + 8];
                #pragma unroll
                for (int nf = 0; nf < 4; nf++) {
                    int bi = (wn*32 + nf*8 + g)*AST + kb;
                    uint32_t bh0 = *(const uint32_t*)&khi[bi];
                    uint32_t bh1 = *(const uint32_t*)&khi[bi + 8];
                    uint32_t bl0 = *(const uint32_t*)&klo[bi];
                    uint32_t bl1 = *(const uint32_t*)&klo[bi + 8];
                    MMA_BF16(acc[nf], ah0, ah1, ah2, ah3, bh0, bh1);
                    MMA_BF16(acc[nf], ah0, ah1, ah2, ah3, bl0, bl1);
                    MMA_BF16(acc[nf], al0, al1, al2, al3, bh0, bh1);
                }
            }
            #pragma unroll
            for (int nf = 0; nf < 4; nf++) {
                int col = wn*32 + nf*8 + 2*tg;
                float2 lo2 = { acc[nf][0], acc[nf][1] };
                float2 hi2 = { acc[nf][2], acc[nf][3] };
                *(float2*)&s_t[(m0+g)*68 + col]   = lo2;
                *(float2*)&s_t[(m0+g+8)*68 + col] = hi2;
            }
        }
        __syncthreads();

        // ---- online softmax (warp w -> rows w*8..w*8+7), P -> bf16 hi/lo ----
        #pragma unroll
        for (int rr = 0; rr < 8; rr++) {
            int q = wid*8 + rr;
            int s = q & 15;
            float v0 = s_t[q*68 + lane]      + msk[s*66 + lane];
            float v1 = s_t[q*68 + lane + 32] + msk[s*66 + lane + 32];
            float mx = fmaxf(v0, v1);
            #pragma unroll
            for (int o = 16; o; o >>= 1) mx = fmaxf(mx, __shfl_xor_sync(0xffffffffu, mx, o));
            float mnew = fmaxf(m_s[q], mx);
            float p0 = __expf(v0 - mnew);
            float p1 = __expf(v1 - mnew);
            uint32_t u0 = __float_as_uint(p0);
            uint32_t u1 = __float_as_uint(p1);
            float h0 = __uint_as_float(u0 & 0xFFFF0000u);
            float h1 = __uint_as_float(u1 & 0xFFFF0000u);
            phi[q*PST + lane]      = (uint16_t)(u0 >> 16);
            phi[q*PST + lane + 32] = (uint16_t)(u1 >> 16);
            plo[q*PST + lane]      = (uint16_t)(__float_as_uint(p0 - h0) >> 16);
            plo[q*PST + lane + 32] = (uint16_t)(__float_as_uint(p1 - h1) >> 16);
            float sum = p0 + p1;
            #pragma unroll
            for (int o = 16; o; o >>= 1) sum += __shfl_xor_sync(0xffffffffu, sum, o);
            if (lane == 0) {
                float sc = __expf(m_s[q] - mnew);
                sc_s[q] = sc;
                l_s[q]  = l_s[q] * sc + sum;
                m_s[q]  = mnew;
            }
        }
        __syncthreads();

        // ---- PV: O[64q][128d] += P @ V, 3 products, k=64 (4 k16 steps) ----
        {
            float sc0 = sc_s[m0 + g];
            float sc1 = sc_s[m0 + g + 8];
            #pragma unroll
            for (int nf = 0; nf < 8; nf++) {
                accO[nf][0] *= sc0; accO[nf][1] *= sc0;
                accO[nf][2] *= sc1; accO[nf][3] *= sc1;
            }
            #pragma unroll
            for (int kk = 0; kk < 4; kk++) {
                const int kb = kk*16 + 2*tg;
                int ai = (m0 + g)*PST + kb;
                uint32_t ah0 = *(const uint32_t*)&phi[ai];
                uint32_t ah1 = *(const uint32_t*)&phi[ai + 8*PST];
                uint32_t ah2 = *(const uint32_t*)&phi[ai + 8];
                uint32_t ah3 = *(const uint32_t*)&phi[ai + 8*PST + 8];
                uint32_t al0 = *(const uint32_t*)&plo[ai];
                uint32_t al1 = *(const uint32_t*)&plo[ai + 8*PST];
                uint32_t al2 = *(const uint32_t*)&plo[ai + 8];
                uint32_t al3 = *(const uint32_t*)&plo[ai + 8*PST + 8];
                #pragma unroll
                for (int dd = 0; dd < 4; dd++) {
                    int d0 = wn*64 + dd*16;
                    uint32_t rowa = (uint32_t)((kk*16 + (lane & 15))*AST
                                    + d0 + (lane >> 4)*8) * 2u;
                    uint32_t bh0, bh1, bh2, bh3, bl0, bl1, bl2, bl3;
                    ldmx4t(bh0, bh1, bh2, bh3, smb + O_VHI + rowa);
                    ldmx4t(bl0, bl1, bl2, bl3, smb + O_VLO + rowa);
                    MMA_BF16(accO[dd*2],   ah0, ah1, ah2, ah3, bh0, bh1);
                    MMA_BF16(accO[dd*2],   al0, al1, al2, al3, bh0, bh1);
                    MMA_BF16(accO[dd*2],   ah0, ah1, ah2, ah3, bl0, bl1);
                    MMA_BF16(accO[dd*2+1], ah0, ah1, ah2, ah3, bh2, bh3);
                    MMA_BF16(accO[dd*2+1], al0, al1, al2, al3, bh2, bh3);
                    MMA_BF16(accO[dd*2+1], ah0, ah1, ah2, ah3, bl2, bl3);
                }
            }
        }
        __syncthreads();
    }

    // ---- write partials ----
    size_t base = ((size_t)(b*NKV + kvh)*NSPLIT + sp)*64;
    #pragma unroll
    for (int nf = 0; nf < 8; nf++) {
        int col = wn*64 + nf*8 + 2*tg;
        float2 lo2 = { accO[nf][0], accO[nf][1] };
        float2 hi2 = { accO[nf][2], accO[nf][3] };
        *(float2*)&po[(base + m0 + g)*128 + col]     = lo2;
        *(float2*)&po[(base + m0 + g + 8)*128 + col] = hi2;
    }
    if (t < 64) {
        pml[(base + t)*2 + 0] = m_s[t];
        pml[(base + t)*2 + 1] = l_s[t];
    }
}

// ---------------------------------------------------------------------------
// Combine split-KV partials -> attn output
// ---------------------------------------------------------------------------
__global__ __launch_bounds__(256) void attn_combine(
    const float* __restrict__ po, const float* __restrict__ pml,
    float* __restrict__ attn_out)
{
    __shared__ float wsm[NSPLIT][64];
    __shared__ float linv[64];
    const int t  = threadIdx.x;
    const int bk = blockIdx.x;
    if (t < 64) {
        float mv[NSPLIT];
        float M = -1e30f;
        #pragma unroll
        for (int i = 0; i < NSPLIT; i++) {
            mv[i] = pml[((size_t)(bk*NSPLIT + i)*64 + t)*2 + 0];
            M = fmaxf(M, mv[i]);
        }
        float L = 0.f;
        #pragma unroll
        for (int i = 0; i < NSPLIT; i++) {
            float w = __expf(mv[i] - M);
            wsm[i][t] = w;
            L += w * pml[((size_t)(bk*NSPLIT + i)*64 + t)*2 + 1];
        }
        linv[t] = 1.f / L;
    }
    __syncthreads();
    const int d  = t & 127;
    const int qh = t >> 7;
    const int b = bk >> 3, kvh = bk & 7;
    for (int q = qh*32; q < qh*32 + 32; q++) {
        float o = 0.f;
        #pragma unroll
        for (int i = 0; i < NSPLIT; i++)
            o += po[((size_t)(bk*NSPLIT + i)*64 + q)*128 + d] * wsm[i][q];
        o *= linv[q];
        int s = q & 15, hh = q >> 4;
        attn_out[(size_t)(b*SEQ + s)*DIM + (kvh*4 + hh)*HD + d] = o;
    }
}

// ---------------------------------------------------------------------------
extern "C" void kernel_launch(void* const* d_in, const int* in_sizes, int n_in,
                              void* d_out, int out_size)
{
    const float* x     = (const float*)d_in[0];
    const float* mask  = (const float*)d_in[1];
    const float* freqs = (const float*)d_in[2];
    const float* ck    = (const float*)d_in[3];
    const float* cv    = (const float*)d_in[4];
    const float* wq    = (const float*)d_in[5];
    const float* wk    = (const float*)d_in[6];
    const float* wv    = (const float*)d_in[7];
    const float* wo    = (const float*)d_in[8];
    float* out = (float*)d_out;

    float *qkv, *attn, *po, *pml;
    cudaGetSymbolAddress((void**)&qkv,  g_qkv);
    cudaGetSymbolAddress((void**)&attn, g_attn);
    cudaGetSymbolAddress((void**)&po,   g_po);
    cudaGetSymbolAddress((void**)&pml,  g_pml);

    static int smem_set = 0;
    if (!smem_set) {
        cudaFuncSetAttribute(gemm_mma, cudaFuncAttributeMaxDynamicSharedMemorySize, GEMM_SMEM);
        cudaFuncSetAttribute(attn_mma, cudaFuncAttributeMaxDynamicSharedMemorySize, ATTN_SMEM);
        smem_set = 1;
    }

    // Fused QKV projection (bf16 mma.sync, split hi+lo) + RoPE epilogue
    gemm_mma<<<NQKV/64, 256, GEMM_SMEM>>>(x, wq, wk, wv, qkv, NQKV, freqs, ROPE_LIM);

    // Cache shift + append
    int cb = (CACHE_ELEMS/4 + 255) / 256;
    cache_update<<<cb, 256>>>(ck, out + CK_OFF, qkv + DIM);
    cache_update<<<cb, 256>>>(cv, out + CV_OFF, qkv + DIM + NKV*HD);

    // Attention (split-KV, tensor core) + combine
    attn_mma<<<dim3(NSPLIT, NKV, BSZ), 256, ATTN_SMEM>>>(
        qkv, out + CK_OFF, out + CV_OFF, mask, po, pml);
    attn_combine<<<BSZ*NKV, 256>>>(po, pml, attn);

    // Output projection (bf16 mma.sync)
    gemm_mma<<<DIM/64, 256, GEMM_SMEM>>>(attn, wo, nullptr, nullptr, out, DIM, nullptr, 0);
}

// round 9
// speedup vs baseline: 3.3001x; 1.0315x over previous
#include <cuda_runtime.h>
#include <cstdint>

#define BSZ 8
#define SEQ 16
#define DIM 4096
#define NH 32
#define NKV 8
#define HD 128
#define CL 4096
#define NT (BSZ*SEQ)                 // 128 tokens
#define NQKV (DIM + 2*NKV*HD)        // 6144
#define ROPE_LIM (DIM + NKV*HD)      // 5120
#define CACHE_ELEMS (BSZ*CL*NKV*HD)
#define CK_OFF ((size_t)NT*DIM)
#define CV_OFF (CK_OFF + CACHE_ELEMS)
#define RSQRT_HD 0.08838834764831845f
#define NSPLIT 8
#define KEYS_PER_SPLIT (CL/NSPLIT)   // 512

typedef unsigned long long ull;

__device__ float g_qkv[(size_t)NT*NQKV];
__device__ float g_attn[(size_t)NT*DIM];
__device__ float g_po[(size_t)BSZ*NKV*NSPLIT*64*128];
__device__ float g_pml[(size_t)BSZ*NKV*NSPLIT*64*2];

// ---- bf16 mma.sync (baseline sm_80+ ISA) ----------------------------------
#define MMA_BF16(d, a0,a1,a2,a3, b0,b1) \
    asm volatile( \
        "mma.sync.aligned.m16n8k16.row.col.f32.bf16.bf16.f32 " \
        "{%0,%1,%2,%3}, {%4,%5,%6,%7}, {%8,%9}, {%0,%1,%2,%3};" \
        : "+f"(d[0]), "+f"(d[1]), "+f"(d[2]), "+f"(d[3]) \
        : "r"(a0), "r"(a1), "r"(a2), "r"(a3), "r"(b0), "r"(b1))

__device__ __forceinline__ void ldmx4t(uint32_t& r0, uint32_t& r1,
                                       uint32_t& r2, uint32_t& r3, uint32_t addr) {
    asm volatile("ldmatrix.sync.aligned.m8n8.x4.trans.shared.b16 {%0,%1,%2,%3}, [%4];"
        : "=r"(r0), "=r"(r1), "=r"(r2), "=r"(r3) : "r"(addr));
}
__device__ __forceinline__ uint32_t smem_u32(const void* p) {
    uint32_t a;
    asm("{ .reg .u64 t; cvta.to.shared.u64 t, %1; cvt.u32.u64 %0, t; }"
        : "=r"(a) : "l"(p));
    return a;
}

// split one float pair -> (hi bf16x2, lo bf16x2); first element in low half
__device__ __forceinline__ void split2(float x, float y, uint32_t& hi, uint32_t& lo) {
    uint32_t ux = __float_as_uint(x), uy = __float_as_uint(y);
    float hx = __uint_as_float(ux & 0xFFFF0000u);
    float hy = __uint_as_float(uy & 0xFFFF0000u);
    hi = __byte_perm(ux, uy, 0x7632);
    lo = __byte_perm(__float_as_uint(x - hx), __float_as_uint(y - hy), 0x7632);
}

// ---------------------------------------------------------------------------
// Tensor-core GEMM (unchanged from R7/R8 — measured good)
// ---------------------------------------------------------------------------
#define BKS 64
#define NSTG (DIM/BKS)          // 64
#define ASTR 72
#define U16_AHI 0
#define U16_ALO (128*ASTR)
#define U16_WHI (2*128*ASTR)
#define U16_WLO (2*128*ASTR + 64*ASTR)
#define GEMM_SMEM ((2*128*ASTR + 2*64*ASTR) * 2)   // 55296 bytes

__global__ __launch_bounds__(256) void gemm_mma(
    const float* __restrict__ A,
    const float* __restrict__ W0, const float* __restrict__ W1,
    const float* __restrict__ W2,
    float* __restrict__ C, int ldc,
    const float* __restrict__ freqs, int ropeLim)
{
    extern __shared__ char smraw[];
    uint16_t* sm16 = (uint16_t*)smraw;

    const int t    = threadIdx.x;
    const int wid  = t >> 5;
    const int lane = t & 31;
    const int g    = lane >> 2;
    const int tg   = lane & 3;
    const int wm   = wid >> 1;
    const int wn   = wid & 1;
    const int n0   = blockIdx.x * 64;

    const float* W = W0; int nr = n0;
    if (W1 != nullptr && n0 >= DIM) {
        if (n0 < DIM + NKV*HD) { W = W1; nr = n0 - DIM; }
        else                   { W = W2; nr = n0 - DIM - NKV*HD; }
    }

    float acc[2][4][4] = {};
    float4 pa[8], pw[4];

    #pragma unroll
    for (int it = 0; it < 8; it++) {
        int v = t + it*256, row = v >> 4, gq = v & 15;
        pa[it] = *(const float4*)(A + (size_t)row * DIM + gq*4);
    }
    #pragma unroll
    for (int it = 0; it < 4; it++) {
        int v = t + it*256, row = v >> 4, gq = v & 15;
        pw[it] = *(const float4*)(W + (size_t)(nr + row) * DIM + gq*4);
    }

    for (int st = 0; st < NSTG; st++) {
        __syncthreads();
        #pragma unroll
        for (int it = 0; it < 8; it++) {
            int v = t + it*256, row = v >> 4, gq = v & 15;
            int idx = row*ASTR + gq*4;
            uint32_t h0, l0, h1, l1;
            split2(pa[it].x, pa[it].y, h0, l0);
            split2(pa[it].z, pa[it].w, h1, l1);
            *(uint32_t*)&sm16[U16_AHI + idx]     = h0;
            *(uint32_t*)&sm16[U16_AHI + idx + 2] = h1;
            *(uint32_t*)&sm16[U16_ALO + idx]     = l0;
            *(uint32_t*)&sm16[U16_ALO + idx + 2] = l1;
        }
        #pragma unroll
        for (int it = 0; it < 4; it++) {
            int v = t + it*256, row = v >> 4, gq = v & 15;
            int idx = row*ASTR + gq*4;
            uint32_t h0, l0, h1, l1;
            split2(pw[it].x, pw[it].y, h0, l0);
            split2(pw[it].z, pw[it].w, h1, l1);
            *(uint32_t*)&sm16[U16_WHI + idx]     = h0;
            *(uint32_t*)&sm16[U16_WHI + idx + 2] = h1;
            *(uint32_t*)&sm16[U16_WLO + idx]     = l0;
            *(uint32_t*)&sm16[U16_WLO + idx + 2] = l1;
        }
        __syncthreads();

        if (st + 1 < NSTG) {
            const int k0 = (st + 1) * BKS;
            #pragma unroll
            for (int it = 0; it < 8; it++) {
                int v = t + it*256, row = v >> 4, gq = v & 15;
                pa[it] = *(const float4*)(A + (size_t)row * DIM + k0 + gq*4);
            }
            #pragma unroll
            for (int it = 0; it < 4; it++) {
                int v = t + it*256, row = v >> 4, gq = v & 15;
                pw[it] = *(const float4*)(W + (size_t)(nr + row) * DIM + k0 + gq*4);
            }
        }

        #pragma unroll
        for (int kk = 0; kk < 4; kk++) {
            const int kb = kk*16 + 2*tg;
            uint32_t bh0[4], bh1[4], bl0[4], bl1[4];
            #pragma unroll
            for (int nt = 0; nt < 4; nt++) {
                int bi = (wn*32 + nt*8 + g)*ASTR + kb;
                bh0[nt] = *(const uint32_t*)&sm16[U16_WHI + bi];
                bh1[nt] = *(const uint32_t*)&sm16[U16_WHI + bi + 8];
                bl0[nt] = *(const uint32_t*)&sm16[U16_WLO + bi];
                bl1[nt] = *(const uint32_t*)&sm16[U16_WLO + bi + 8];
            }
            #pragma unroll
            for (int mh = 0; mh < 2; mh++) {
                int ai = (wm*32 + mh*16 + g)*ASTR + kb;
                uint32_t ah0 = *(const uint32_t*)&sm16[U16_AHI + ai];
                uint32_t ah1 = *(const uint32_t*)&sm16[U16_AHI + ai + 8*ASTR];
                uint32_t ah2 = *(const uint32_t*)&sm16[U16_AHI + ai + 8];
                uint32_t ah3 = *(const uint32_t*)&sm16[U16_AHI + ai + 8*ASTR + 8];
                uint32_t al0 = *(const uint32_t*)&sm16[U16_ALO + ai];
                uint32_t al1 = *(const uint32_t*)&sm16[U16_ALO + ai + 8*ASTR];
                uint32_t al2 = *(const uint32_t*)&sm16[U16_ALO + ai + 8];
                uint32_t al3 = *(const uint32_t*)&sm16[U16_ALO + ai + 8*ASTR + 8];
                #pragma unroll
                for (int nt = 0; nt < 4; nt++) {
                    MMA_BF16(acc[mh][nt], ah0, ah1, ah2, ah3, bh0[nt], bh1[nt]);
                    MMA_BF16(acc[mh][nt], ah0, ah1, ah2, ah3, bl0[nt], bl1[nt]);
                    MMA_BF16(acc[mh][nt], al0, al1, al2, al3, bh0[nt], bh1[nt]);
                }
            }
        }
    }

    const bool doRope = n0 < ropeLim;
    #pragma unroll
    for (int mh = 0; mh < 2; mh++) {
        #pragma unroll
        for (int nt = 0; nt < 4; nt++) {
            int r0 = wm*32 + mh*16 + g;
            int r1 = r0 + 8;
            int gc = n0 + wn*32 + nt*8 + 2*tg;
            float v0 = acc[mh][nt][0], v1 = acc[mh][nt][1];
            float v2 = acc[mh][nt][2], v3 = acc[mh][nt][3];
            float2 o0, o1;
            if (doRope) {
                int pd2 = (gc & (HD-1)) >> 1;
                const float* f0 = freqs + (r0 & (SEQ-1))*128 + pd2*2;
                const float* f1 = freqs + (r1 & (SEQ-1))*128 + pd2*2;
                float ca0 = f0[0], sa0 = f0[1];
                float ca1 = f1[0], sa1 = f1[1];
                o0.x = v0*ca0 - v1*sa0;  o0.y = v0*sa0 + v1*ca0;
                o1.x = v2*ca1 - v3*sa1;  o1.y = v2*sa1 + v3*ca1;
            } else {
                o0.x = v0; o0.y = v1; o1.x = v2; o1.y = v3;
            }
            *(float2*)&C[(size_t)r0 * ldc + gc] = o0;
            *(float2*)&C[(size_t)r1 * ldc + gc] = o1;
        }
    }
}

// ---------------------------------------------------------------------------
// Cache shift + append: fused K+V (blockIdx.y selects stream)
// ---------------------------------------------------------------------------
__global__ __launch_bounds__(256) void cache_update2(
    const float* __restrict__ ck, const float* __restrict__ cv,
    float* __restrict__ outk, float* __restrict__ outv,
    const float* __restrict__ qkvp)
{
    const int total = CACHE_ELEMS / 4;
    int i = blockIdx.x * 256 + threadIdx.x;
    if (i >= total) return;
    const float* cin;
    float* cout;
    const float* src;
    if (blockIdx.y == 0) { cin = ck; cout = outk; src = qkvp + DIM; }
    else                 { cin = cv; cout = outv; src = qkvp + DIM + NKV*HD; }
    const int ROW4 = NKV * HD / 4;
    int b    = i / (CL * ROW4);
    int r    = i % (CL * ROW4);
    int tpos = r / ROW4;
    int c    = r % ROW4;
    float4 v;
    if (tpos < CL - SEQ) {
        v = ((const float4*)cin)[(size_t)(b * CL + tpos + SEQ) * ROW4 + c];
    } else {
        int s   = tpos - (CL - SEQ);
        int tok = b * SEQ + s;
        v = *(const float4*)(src + (size_t)tok * NQKV + c * 4);
    }
    ((float4*)cout)[i] = v;
}

// ---------------------------------------------------------------------------
// Attention via mma.sync split-bf16, chunk=32, 2 CTAs/SM.
// grid (NSPLIT, NKV, BSZ), 256 threads. 64 q over 512 keys.
// ---------------------------------------------------------------------------
#define AST 136     // u16 stride for 128-wide tiles (q, K, V)
#define PST 40      // u16 stride for P (32 keys)
#define CHK 32

#define O_QHI 0
#define O_QLO (O_QHI + 17408)
#define O_KHI (O_QLO + 17408)     // 32*136*2 = 8704
#define O_KLO (O_KHI + 8704)
#define O_VHI (O_KLO + 8704)
#define O_VLO (O_VHI + 8704)
#define O_ST  (O_VLO + 8704)      // f32 [64][36] = 9216
#define O_PHI (O_ST  + 9216)      // u16 [64][40] = 5120
#define O_PLO (O_PHI + 5120)
#define O_MS  (O_PLO + 5120)
#define O_LS  (O_MS  + 256)
#define O_SCS (O_LS  + 256)
#define ATTN_SMEM (O_SCS + 256)   // 90112 bytes -> 2 CTAs/SM

__global__ __launch_bounds__(256, 2) void attn_mma(
    const float* __restrict__ qkv, const float* __restrict__ Kc,
    const float* __restrict__ Vc, const float* __restrict__ mask,
    float* __restrict__ po, float* __restrict__ pml)
{
    extern __shared__ char sm[];
    uint16_t* qhi = (uint16_t*)(sm + O_QHI);
    uint16_t* qlo = (uint16_t*)(sm + O_QLO);
    uint16_t* khi = (uint16_t*)(sm + O_KHI);
    uint16_t* klo = (uint16_t*)(sm + O_KLO);
    uint16_t* vhi = (uint16_t*)(sm + O_VHI);
    uint16_t* vlo = (uint16_t*)(sm + O_VLO);
    float*    s_t = (float*)(sm + O_ST);
    uint16_t* phi = (uint16_t*)(sm + O_PHI);
    uint16_t* plo = (uint16_t*)(sm + O_PLO);
    float*    m_s = (float*)(sm + O_MS);
    float*    l_s = (float*)(sm + O_LS);
    float*    sc_s= (float*)(sm + O_SCS);
    const uint32_t smb = smem_u32(sm);

    const int t    = threadIdx.x;
    const int wid  = t >> 5;
    const int lane = t & 31;
    const int g    = lane >> 2;
    const int tg   = lane & 3;
    const int wm   = wid >> 1;           // 0..3 -> m0 = wm*16
    const int wn   = wid & 1;
    const int m0   = wm * 16;
    const int sp   = blockIdx.x;
    const int kvh  = blockIdx.y;
    const int b    = blockIdx.z;
    const int key0 = sp * KEYS_PER_SPLIT;

    // ---- q load + scale + split (once per block) ----
    #pragma unroll
    for (int it = 0; it < 8; it++) {
        int idx = t + it*256;          // 2048 float4
        int q = idx >> 5, dq = idx & 31;
        const float* src = qkv + (size_t)(b*SEQ + (q & 15))*NQKV
                           + (kvh*4 + (q >> 4))*HD + dq*4;
        float4 v = *(const float4*)src;
        v.x *= RSQRT_HD; v.y *= RSQRT_HD; v.z *= RSQRT_HD; v.w *= RSQRT_HD;
        uint32_t h0, l0, h1, l1;
        split2(v.x, v.y, h0, l0);
        split2(v.z, v.w, h1, l1);
        int o = q*AST + dq*4;
        *(uint32_t*)&qhi[o] = h0;   *(uint32_t*)&qhi[o+2] = h1;
        *(uint32_t*)&qlo[o] = l0;   *(uint32_t*)&qlo[o+2] = l1;
    }
    if (t < 64) { m_s[t] = -1e30f; l_s[t] = 0.f; }

    float accO[8][4] = {};

    for (int c0 = 0; c0 < KEYS_PER_SPLIT; c0 += CHK) {
        // ---- K, V chunk conversion (32 keys) ----
        #pragma unroll
        for (int it = 0; it < 4; it++) {
            int idx = t + it*256;          // 1024 float4
            int key = idx >> 5, dq = idx & 31;
            size_t gofs = ((size_t)(b*CL + key0 + c0 + key)*NKV + kvh)*HD + dq*4;
            float4 kv = *(const float4*)(Kc + gofs);
            float4 vv = *(const float4*)(Vc + gofs);
            uint32_t h0, l0, h1, l1;
            int o = key*AST + dq*4;
            split2(kv.x, kv.y, h0, l0); split2(kv.z, kv.w, h1, l1);
            *(uint32_t*)&khi[o] = h0;  *(uint32_t*)&khi[o+2] = h1;
            *(uint32_t*)&klo[o] = l0;  *(uint32_t*)&klo[o+2] = l1;
            split2(vv.x, vv.y, h0, l0); split2(vv.z, vv.w, h1, l1);
            *(uint32_t*)&vhi[o] = h0;  *(uint32_t*)&vhi[o+2] = h1;
            *(uint32_t*)&vlo[o] = l0;  *(uint32_t*)&vlo[o+2] = l1;
        }
        __syncthreads();

        // ---- QK: scores[64q][32keys], 3 products, K=128 (8 k16 steps) ----
        {
            float acc[2][4] = {};
            #pragma unroll
            for (int kk = 0; kk < 8; kk++) {
                const int kb = kk*16 + 2*tg;
                int ai = (m0 + g)*AST + kb;
                uint32_t ah0 = *(const uint32_t*)&qhi[ai];
                uint32_t ah1 = *(const uint32_t*)&qhi[ai + 8*AST];
                uint32_t ah2 = *(const uint32_t*)&qhi[ai + 8];
                uint32_t ah3 = *(const uint32_t*)&qhi[ai + 8*AST + 8];
                uint32_t al0 = *(const uint32_t*)&qlo[ai];
                uint32_t al1 = *(const uint32_t*)&qlo[ai + 8*AST];
                uint32_t al2 = *(const uint32_t*)&qlo[ai + 8];
                uint32_t al3 = *(const uint32_t*)&qlo[ai + 8*AST + 8];
                #pragma unroll
                for (int nf = 0; nf < 2; nf++) {
                    int bi = (wn*16 + nf*8 + g)*AST + kb;
                    uint32_t bh0 = *(const uint32_t*)&khi[bi];
                    uint32_t bh1 = *(const uint32_t*)&khi[bi + 8];
                    uint32_t bl0 = *(const uint32_t*)&klo[bi];
                    uint32_t bl1 = *(const uint32_t*)&klo[bi + 8];
                    MMA_BF16(acc[nf], ah0, ah1, ah2, ah3, bh0, bh1);
                    MMA_BF16(acc[nf], ah0, ah1, ah2, ah3, bl0, bl1);
                    MMA_BF16(acc[nf], al0, al1, al2, al3, bh0, bh1);
                }
            }
            #pragma unroll
            for (int nf = 0; nf < 2; nf++) {
                int col = wn*16 + nf*8 + 2*tg;
                float2 lo2 = { acc[nf][0], acc[nf][1] };
                float2 hi2 = { acc[nf][2], acc[nf][3] };
                *(float2*)&s_t[(m0+g)*36 + col]   = lo2;
                *(float2*)&s_t[(m0+g+8)*36 + col] = hi2;
            }
        }
        __syncthreads();

        // ---- online softmax (warp w -> rows w*8..w*8+7), P -> bf16 hi/lo ----
        #pragma unroll
        for (int rr = 0; rr < 8; rr++) {
            int q = wid*8 + rr;
            int s = q & 15;
            float v0 = s_t[q*36 + lane] + mask[(size_t)s*CL + key0 + c0 + lane];
            float mx = v0;
            #pragma unroll
            for (int o = 16; o; o >>= 1) mx = fmaxf(mx, __shfl_xor_sync(0xffffffffu, mx, o));
            float mnew = fmaxf(m_s[q], mx);
            float p0 = __expf(v0 - mnew);
            uint32_t u0 = __float_as_uint(p0);
            float h0 = __uint_as_float(u0 & 0xFFFF0000u);
            phi[q*PST + lane] = (uint16_t)(u0 >> 16);
            plo[q*PST + lane] = (uint16_t)(__float_as_uint(p0 - h0) >> 16);
            float sum = p0;
            #pragma unroll
            for (int o = 16; o; o >>= 1) sum += __shfl_xor_sync(0xffffffffu, sum, o);
            if (lane == 0) {
                float sc = __expf(m_s[q] - mnew);
                sc_s[q] = sc;
                l_s[q]  = l_s[q] * sc + sum;
                m_s[q]  = mnew;
            }
        }
        __syncthreads();

        // ---- PV: O[64q][128d] += P @ V, 3 products, k=32 (2 k16 steps) ----
        {
            float sc0 = sc_s[m0 + g];
            float sc1 = sc_s[m0 + g + 8];
            #pragma unroll
            for (int nf = 0; nf < 8; nf++) {
                accO[nf][0] *= sc0; accO[nf][1] *= sc0;
                accO[nf][2] *= sc1; accO[nf][3] *= sc1;
            }
            #pragma unroll
            for (int kk = 0; kk < 2; kk++) {
                const int kb = kk*16 + 2*tg;
                int ai = (m0 + g)*PST + kb;
                uint32_t ah0 = *(const uint32_t*)&phi[ai];
                uint32_t ah1 = *(const uint32_t*)&phi[ai + 8*PST];
                uint32_t ah2 = *(const uint32_t*)&phi[ai + 8];
                uint32_t ah3 = *(const uint32_t*)&phi[ai + 8*PST + 8];
                uint32_t al0 = *(const uint32_t*)&plo[ai];
                uint32_t al1 = *(const uint32_t*)&plo[ai + 8*PST];
                uint32_t al2 = *(const uint32_t*)&plo[ai + 8];
                uint32_t al3 = *(const uint32_t*)&plo[ai + 8*PST + 8];
                #pragma unroll
                for (int dd = 0; dd < 4; dd++) {
                    int d0 = wn*64 + dd*16;
                    uint32_t rowa = (uint32_t)((kk*16 + (lane & 15))*AST
                                    + d0 + (lane >> 4)*8) * 2u;
                    uint32_t bh0, bh1, bh2, bh3, bl0, bl1, bl2, bl3;
                    ldmx4t(bh0, bh1, bh2, bh3, smb + O_VHI + rowa);
                    ldmx4t(bl0, bl1, bl2, bl3, smb + O_VLO + rowa);
                    MMA_BF16(accO[dd*2],   ah0, ah1, ah2, ah3, bh0, bh1);
                    MMA_BF16(accO[dd*2],   al0, al1, al2, al3, bh0, bh1);
                    MMA_BF16(accO[dd*2],   ah0, ah1, ah2, ah3, bl0, bl1);
                    MMA_BF16(accO[dd*2+1], ah0, ah1, ah2, ah3, bh2, bh3);
                    MMA_BF16(accO[dd*2+1], al0, al1, al2, al3, bh2, bh3);
                    MMA_BF16(accO[dd*2+1], ah0, ah1, ah2, ah3, bl2, bl3);
                }
            }
        }
        __syncthreads();
    }

    // ---- write partials ----
    size_t base = ((size_t)(b*NKV + kvh)*NSPLIT + sp)*64;
    #pragma unroll
    for (int nf = 0; nf < 8; nf++) {
        int col = wn*64 + nf*8 + 2*tg;
        float2 lo2 = { accO[nf][0], accO[nf][1] };
        float2 hi2 = { accO[nf][2], accO[nf][3] };
        *(float2*)&po[(base + m0 + g)*128 + col]     = lo2;
        *(float2*)&po[(base + m0 + g + 8)*128 + col] = hi2;
    }
    if (t < 64) {
        pml[(base + t)*2 + 0] = m_s[t];
        pml[(base + t)*2 + 1] = l_s[t];
    }
}

// ---------------------------------------------------------------------------
// Combine split-KV partials -> attn output
// ---------------------------------------------------------------------------
__global__ __launch_bounds__(256) void attn_combine(
    const float* __restrict__ po, const float* __restrict__ pml,
    float* __restrict__ attn_out)
{
    __shared__ float wsm[NSPLIT][64];
    __shared__ float linv[64];
    const int t  = threadIdx.x;
    const int bk = blockIdx.x;
    if (t < 64) {
        float mv[NSPLIT];
        float M = -1e30f;
        #pragma unroll
        for (int i = 0; i < NSPLIT; i++) {
            mv[i] = pml[((size_t)(bk*NSPLIT + i)*64 + t)*2 + 0];
            M = fmaxf(M, mv[i]);
        }
        float L = 0.f;
        #pragma unroll
        for (int i = 0; i < NSPLIT; i++) {
            float w = __expf(mv[i] - M);
            wsm[i][t] = w;
            L += w * pml[((size_t)(bk*NSPLIT + i)*64 + t)*2 + 1];
        }
        linv[t] = 1.f / L;
    }
    __syncthreads();
    const int d  = t & 127;
    const int qh = t >> 7;
    const int b = bk >> 3, kvh = bk & 7;
    for (int q = qh*32; q < qh*32 + 32; q++) {
        float o = 0.f;
        #pragma unroll
        for (int i = 0; i < NSPLIT; i++)
            o += po[((size_t)(bk*NSPLIT + i)*64 + q)*128 + d] * wsm[i][q];
        o *= linv[q];
        int s = q & 15, hh = q >> 4;
        attn_out[(size_t)(b*SEQ + s)*DIM + (kvh*4 + hh)*HD + d] = o;
    }
}

// ---------------------------------------------------------------------------
extern "C" void kernel_launch(void* const* d_in, const int* in_sizes, int n_in,
                              void* d_out, int out_size)
{
    const float* x     = (const float*)d_in[0];
    const float* mask  = (const float*)d_in[1];
    const float* freqs = (const float*)d_in[2];
    const float* ck    = (const float*)d_in[3];
    const float* cv    = (const float*)d_in[4];
    const float* wq    = (const float*)d_in[5];
    const float* wk    = (const float*)d_in[6];
    const float* wv    = (const float*)d_in[7];
    const float* wo    = (const float*)d_in[8];
    float* out = (float*)d_out;

    float *qkv, *attn, *po, *pml;
    cudaGetSymbolAddress((void**)&qkv,  g_qkv);
    cudaGetSymbolAddress((void**)&attn, g_attn);
    cudaGetSymbolAddress((void**)&po,   g_po);
    cudaGetSymbolAddress((void**)&pml,  g_pml);

    static int smem_set = 0;
    if (!smem_set) {
        cudaFuncSetAttribute(gemm_mma, cudaFuncAttributeMaxDynamicSharedMemorySize, GEMM_SMEM);
        cudaFuncSetAttribute(attn_mma, cudaFuncAttributeMaxDynamicSharedMemorySize, ATTN_SMEM);
        smem_set = 1;
    }

    // Fused QKV projection (bf16 mma.sync, split hi+lo) + RoPE epilogue
    gemm_mma<<<NQKV/64, 256, GEMM_SMEM>>>(x, wq, wk, wv, qkv, NQKV, freqs, ROPE_LIM);

    // Cache shift + append (K and V in one launch)
    int cb = (CACHE_ELEMS/4 + 255) / 256;
    cache_update2<<<dim3(cb, 2), 256>>>(ck, cv, out + CK_OFF, out + CV_OFF, qkv);

    // Attention (split-KV, tensor core, 2 CTAs/SM) + combine
    attn_mma<<<dim3(NSPLIT, NKV, BSZ), 256, ATTN_SMEM>>>(
        qkv, out + CK_OFF, out + CV_OFF, mask, po, pml);
    attn_combine<<<BSZ*NKV, 256>>>(po, pml, attn);

    // Output projection (bf16 mma.sync)
    gemm_mma<<<DIM/64, 256, GEMM_SMEM>>>(attn, wo, nullptr, nullptr, out, DIM, nullptr, 0);
}

// round 10
// speedup vs baseline: 3.6273x; 1.0991x over previous
#include <cuda_runtime.h>
#include <cstdint>

#define BSZ 8
#define SEQ 16
#define DIM 4096
#define NH 32
#define NKV 8
#define HD 128
#define CL 4096
#define NT (BSZ*SEQ)                 // 128 tokens
#define NQKV (DIM + 2*NKV*HD)        // 6144
#define ROPE_LIM (DIM + NKV*HD)      // 5120
#define CACHE_ELEMS (BSZ*CL*NKV*HD)
#define CK_OFF ((size_t)NT*DIM)
#define CV_OFF (CK_OFF + CACHE_ELEMS)
#define RSQRT_HD 0.08838834764831845f
#define NSPLIT 8
#define KEYS_PER_SPLIT (CL/NSPLIT)   // 512

typedef unsigned long long ull;

__device__ float g_qkv[(size_t)NT*NQKV];
__device__ float g_attn[(size_t)NT*DIM];
__device__ float g_po[(size_t)BSZ*NKV*NSPLIT*64*128];
__device__ float g_pml[(size_t)BSZ*NKV*NSPLIT*64*2];

// ---- bf16 mma.sync (baseline sm_80+ ISA) ----------------------------------
#define MMA_BF16(d, a0,a1,a2,a3, b0,b1) \
    asm volatile( \
        "mma.sync.aligned.m16n8k16.row.col.f32.bf16.bf16.f32 " \
        "{%0,%1,%2,%3}, {%4,%5,%6,%7}, {%8,%9}, {%0,%1,%2,%3};" \
        : "+f"(d[0]), "+f"(d[1]), "+f"(d[2]), "+f"(d[3]) \
        : "r"(a0), "r"(a1), "r"(a2), "r"(a3), "r"(b0), "r"(b1))

__device__ __forceinline__ void ldmx4t(uint32_t& r0, uint32_t& r1,
                                       uint32_t& r2, uint32_t& r3, uint32_t addr) {
    asm volatile("ldmatrix.sync.aligned.m8n8.x4.trans.shared.b16 {%0,%1,%2,%3}, [%4];"
        : "=r"(r0), "=r"(r1), "=r"(r2), "=r"(r3) : "r"(addr));
}
__device__ __forceinline__ uint32_t smem_u32(const void* p) {
    uint32_t a;
    asm("{ .reg .u64 t; cvta.to.shared.u64 t, %1; cvt.u32.u64 %0, t; }"
        : "=r"(a) : "l"(p));
    return a;
}
__device__ __forceinline__ void cpasync16(uint32_t dst, const void* src) {
    asm volatile("cp.async.cg.shared.global [%0], [%1], 16;"
                 :: "r"(dst), "l"(src) : "memory");
}
#define CP_COMMIT() asm volatile("cp.async.commit_group;" ::: "memory")
#define CP_WAIT0()  asm volatile("cp.async.wait_group 0;" ::: "memory")

// split one float pair -> (hi bf16x2, lo bf16x2); first element in low half
__device__ __forceinline__ void split2(float x, float y, uint32_t& hi, uint32_t& lo) {
    uint32_t ux = __float_as_uint(x), uy = __float_as_uint(y);
    float hx = __uint_as_float(ux & 0xFFFF0000u);
    float hy = __uint_as_float(uy & 0xFFFF0000u);
    hi = __byte_perm(ux, uy, 0x7632);
    lo = __byte_perm(__float_as_uint(x - hx), __float_as_uint(y - hy), 0x7632);
}

// ---------------------------------------------------------------------------
// Tensor-core GEMM (split-bf16 mma.sync), templated on BN (64 or 32).
// ---------------------------------------------------------------------------
#define BKS 64
#define NSTG (DIM/BKS)          // 64
#define ASTR 72
#define U16_AHI 0
#define U16_ALO (128*ASTR)
#define U16_WHI (2*128*ASTR)

template<int BN>
__global__ __launch_bounds__(256) void gemm_mma(
    const float* __restrict__ A,
    const float* __restrict__ W0, const float* __restrict__ W1,
    const float* __restrict__ W2,
    float* __restrict__ C, int ldc,
    const float* __restrict__ freqs, int ropeLim)
{
    extern __shared__ char smraw[];
    uint16_t* sm16 = (uint16_t*)smraw;
    constexpr int MH = BN / 32;                // 2 for BN=64, 1 for BN=32
    constexpr int WLO = 2*128*ASTR + BN*ASTR;

    const int t    = threadIdx.x;
    const int wid  = t >> 5;
    const int lane = t & 31;
    const int g    = lane >> 2;
    const int tg   = lane & 3;
    const int wm   = (BN == 64) ? (wid >> 1) : wid;
    const int wn   = (BN == 64) ? (wid & 1) : 0;
    const int n0   = blockIdx.x * BN;

    const float* W = W0; int nr = n0;
    if (W1 != nullptr && n0 >= DIM) {
        if (n0 < DIM + NKV*HD) { W = W1; nr = n0 - DIM; }
        else                   { W = W2; nr = n0 - DIM - NKV*HD; }
    }

    float acc[MH][4][4] = {};
    float4 pa[8], pw[BN/16];

    #pragma unroll
    for (int it = 0; it < 8; it++) {
        int v = t + it*256, row = v >> 4, gq = v & 15;
        pa[it] = *(const float4*)(A + (size_t)row * DIM + gq*4);
    }
    #pragma unroll
    for (int it = 0; it < BN/16; it++) {
        int v = t + it*256, row = v >> 4, gq = v & 15;
        pw[it] = *(const float4*)(W + (size_t)(nr + row) * DIM + gq*4);
    }

    for (int st = 0; st < NSTG; st++) {
        __syncthreads();
        #pragma unroll
        for (int it = 0; it < 8; it++) {
            int v = t + it*256, row = v >> 4, gq = v & 15;
            int idx = row*ASTR + gq*4;
            uint32_t h0, l0, h1, l1;
            split2(pa[it].x, pa[it].y, h0, l0);
            split2(pa[it].z, pa[it].w, h1, l1);
            *(uint32_t*)&sm16[U16_AHI + idx]     = h0;
            *(uint32_t*)&sm16[U16_AHI + idx + 2] = h1;
            *(uint32_t*)&sm16[U16_ALO + idx]     = l0;
            *(uint32_t*)&sm16[U16_ALO + idx + 2] = l1;
        }
        #pragma unroll
        for (int it = 0; it < BN/16; it++) {
            int v = t + it*256, row = v >> 4, gq = v & 15;
            int idx = row*ASTR + gq*4;
            uint32_t h0, l0, h1, l1;
            split2(pw[it].x, pw[it].y, h0, l0);
            split2(pw[it].z, pw[it].w, h1, l1);
            *(uint32_t*)&sm16[U16_WHI + idx]     = h0;
            *(uint32_t*)&sm16[U16_WHI + idx + 2] = h1;
            *(uint32_t*)&sm16[WLO + idx]     = l0;
            *(uint32_t*)&sm16[WLO + idx + 2] = l1;
        }
        __syncthreads();

        if (st + 1 < NSTG) {
            const int k0 = (st + 1) * BKS;
            #pragma unroll
            for (int it = 0; it < 8; it++) {
                int v = t + it*256, row = v >> 4, gq = v & 15;
                pa[it] = *(const float4*)(A + (size_t)row * DIM + k0 + gq*4);
            }
            #pragma unroll
            for (int it = 0; it < BN/16; it++) {
                int v = t + it*256, row = v >> 4, gq = v & 15;
                pw[it] = *(const float4*)(W + (size_t)(nr + row) * DIM + k0 + gq*4);
            }
        }

        #pragma unroll
        for (int kk = 0; kk < 4; kk++) {
            const int kb = kk*16 + 2*tg;
            uint32_t bh0[4], bh1[4], bl0[4], bl1[4];
            #pragma unroll
            for (int nt = 0; nt < 4; nt++) {
                int bi = (wn*32 + nt*8 + g)*ASTR + kb;
                bh0[nt] = *(const uint32_t*)&sm16[U16_WHI + bi];
                bh1[nt] = *(const uint32_t*)&sm16[U16_WHI + bi + 8];
                bl0[nt] = *(const uint32_t*)&sm16[WLO + bi];
                bl1[nt] = *(const uint32_t*)&sm16[WLO + bi + 8];
            }
            #pragma unroll
            for (int mh = 0; mh < MH; mh++) {
                int ai = (wm*16*MH + mh*16 + g)*ASTR + kb;
                uint32_t ah0 = *(const uint32_t*)&sm16[U16_AHI + ai];
                uint32_t ah1 = *(const uint32_t*)&sm16[U16_AHI + ai + 8*ASTR];
                uint32_t ah2 = *(const uint32_t*)&sm16[U16_AHI + ai + 8];
                uint32_t ah3 = *(const uint32_t*)&sm16[U16_AHI + ai + 8*ASTR + 8];
                uint32_t al0 = *(const uint32_t*)&sm16[U16_ALO + ai];
                uint32_t al1 = *(const uint32_t*)&sm16[U16_ALO + ai + 8*ASTR];
                uint32_t al2 = *(const uint32_t*)&sm16[U16_ALO + ai + 8];
                uint32_t al3 = *(const uint32_t*)&sm16[U16_ALO + ai + 8*ASTR + 8];
                #pragma unroll
                for (int nt = 0; nt < 4; nt++) {
                    MMA_BF16(acc[mh][nt], ah0, ah1, ah2, ah3, bh0[nt], bh1[nt]);
                    MMA_BF16(acc[mh][nt], ah0, ah1, ah2, ah3, bl0[nt], bl1[nt]);
                    MMA_BF16(acc[mh][nt], al0, al1, al2, al3, bh0[nt], bh1[nt]);
                }
            }
        }
    }

    const bool doRope = n0 < ropeLim;
    #pragma unroll
    for (int mh = 0; mh < MH; mh++) {
        #pragma unroll
        for (int nt = 0; nt < 4; nt++) {
            int r0 = wm*16*MH + mh*16 + g;
            int r1 = r0 + 8;
            int gc = n0 + wn*32 + nt*8 + 2*tg;
            float v0 = acc[mh][nt][0], v1 = acc[mh][nt][1];
            float v2 = acc[mh][nt][2], v3 = acc[mh][nt][3];
            float2 o0, o1;
            if (doRope) {
                int pd2 = (gc & (HD-1)) >> 1;
                const float* f0 = freqs + (r0 & (SEQ-1))*128 + pd2*2;
                const float* f1 = freqs + (r1 & (SEQ-1))*128 + pd2*2;
                float ca0 = f0[0], sa0 = f0[1];
                float ca1 = f1[0], sa1 = f1[1];
                o0.x = v0*ca0 - v1*sa0;  o0.y = v0*sa0 + v1*ca0;
                o1.x = v2*ca1 - v3*sa1;  o1.y = v2*sa1 + v3*ca1;
            } else {
                o0.x = v0; o0.y = v1; o1.x = v2; o1.y = v3;
            }
            *(float2*)&C[(size_t)r0 * ldc + gc] = o0;
            *(float2*)&C[(size_t)r1 * ldc + gc] = o1;
        }
    }
}

// ---------------------------------------------------------------------------
// Cache shift + append: fused K+V (blockIdx.y selects stream)
// ---------------------------------------------------------------------------
__global__ __launch_bounds__(256) void cache_update2(
    const float* __restrict__ ck, const float* __restrict__ cv,
    float* __restrict__ outk, float* __restrict__ outv,
    const float* __restrict__ qkvp)
{
    const int total = CACHE_ELEMS / 4;
    int i = blockIdx.x * 256 + threadIdx.x;
    if (i >= total) return;
    const float* cin;
    float* cout;
    const float* src;
    if (blockIdx.y == 0) { cin = ck; cout = outk; src = qkvp + DIM; }
    else                 { cin = cv; cout = outv; src = qkvp + DIM + NKV*HD; }
    const int ROW4 = NKV * HD / 4;
    int b    = i / (CL * ROW4);
    int r    = i % (CL * ROW4);
    int tpos = r / ROW4;
    int c    = r % ROW4;
    float4 v;
    if (tpos < CL - SEQ) {
        v = ((const float4*)cin)[(size_t)(b * CL + tpos + SEQ) * ROW4 + c];
    } else {
        int s   = tpos - (CL - SEQ);
        int tok = b * SEQ + s;
        v = *(const float4*)(src + (size_t)tok * NQKV + c * 4);
    }
    ((float4*)cout)[i] = v;
}

// ---------------------------------------------------------------------------
// Attention via mma.sync split-bf16, chunk=32, 2 CTAs/SM, cp.async K staging.
// grid (NSPLIT, NKV, BSZ), 256 threads. 64 q over 512 keys.
// ---------------------------------------------------------------------------
#define AST 136     // u16 stride for 128-wide tiles (q, K, V)
#define PST 40      // u16 stride for P (32 keys)
#define CHK 32

#define O_QHI 0
#define O_QLO (O_QHI + 17408)
#define O_KHI (O_QLO + 17408)     // 32*136*2 = 8704
#define O_KLO (O_KHI + 8704)
#define O_VHI (O_KLO + 8704)
#define O_VLO (O_VHI + 8704)
#define O_ST  (O_VLO + 8704)      // f32 [64][36] = 9216
#define O_PHI (O_ST  + 9216)      // u16 [64][40] = 5120
#define O_PLO (O_PHI + 5120)
#define O_MS  (O_PLO + 5120)
#define O_LS  (O_MS  + 256)
#define O_SCS (O_LS  + 256)
#define O_STG (O_SCS + 256)       // raw fp32 K stage: 32*128*4 = 16384
#define ATTN_SMEM (O_STG + 16384) // 106496 bytes -> 2 CTAs/SM (213KB/228KB)

__global__ __launch_bounds__(256, 2) void attn_mma(
    const float* __restrict__ qkv, const float* __restrict__ Kc,
    const float* __restrict__ Vc, const float* __restrict__ mask,
    float* __restrict__ po, float* __restrict__ pml)
{
    extern __shared__ char sm[];
    uint16_t* qhi = (uint16_t*)(sm + O_QHI);
    uint16_t* qlo = (uint16_t*)(sm + O_QLO);
    uint16_t* khi = (uint16_t*)(sm + O_KHI);
    uint16_t* klo = (uint16_t*)(sm + O_KLO);
    uint16_t* vhi = (uint16_t*)(sm + O_VHI);
    uint16_t* vlo = (uint16_t*)(sm + O_VLO);
    float*    s_t = (float*)(sm + O_ST);
    uint16_t* phi = (uint16_t*)(sm + O_PHI);
    uint16_t* plo = (uint16_t*)(sm + O_PLO);
    float*    m_s = (float*)(sm + O_MS);
    float*    l_s = (float*)(sm + O_LS);
    float*    sc_s= (float*)(sm + O_SCS);
    const float4* stg4 = (const float4*)(sm + O_STG);
    const uint32_t smb = smem_u32(sm);

    const int t    = threadIdx.x;
    const int wid  = t >> 5;
    const int lane = t & 31;
    const int g    = lane >> 2;
    const int tg   = lane & 3;
    const int wm   = wid >> 1;           // 0..3 -> m0 = wm*16
    const int wn   = wid & 1;
    const int m0   = wm * 16;
    const int sp   = blockIdx.x;
    const int kvh  = blockIdx.y;
    const int b    = blockIdx.z;
    const int key0 = sp * KEYS_PER_SPLIT;

    // ---- q load + scale + split (once per block) ----
    #pragma unroll
    for (int it = 0; it < 8; it++) {
        int idx = t + it*256;          // 2048 float4
        int q = idx >> 5, dq = idx & 31;
        const float* src = qkv + (size_t)(b*SEQ + (q & 15))*NQKV
                           + (kvh*4 + (q >> 4))*HD + dq*4;
        float4 v = *(const float4*)src;
        v.x *= RSQRT_HD; v.y *= RSQRT_HD; v.z *= RSQRT_HD; v.w *= RSQRT_HD;
        uint32_t h0, l0, h1, l1;
        split2(v.x, v.y, h0, l0);
        split2(v.z, v.w, h1, l1);
        int o = q*AST + dq*4;
        *(uint32_t*)&qhi[o] = h0;   *(uint32_t*)&qhi[o+2] = h1;
        *(uint32_t*)&qlo[o] = l0;   *(uint32_t*)&qlo[o+2] = l1;
    }
    if (t < 64) { m_s[t] = -1e30f; l_s[t] = 0.f; }

    // ---- prologue: stage chunk 0's K via cp.async ----
    #pragma unroll
    for (int it = 0; it < 4; it++) {
        int idx = t + it*256;
        int key = idx >> 5, dq = idx & 31;
        const float* src = Kc + ((size_t)(b*CL + key0 + key)*NKV + kvh)*HD + dq*4;
        cpasync16(smb + O_STG + (uint32_t)idx*16, src);
    }
    CP_COMMIT();

    float accO[8][4] = {};

    for (int c0 = 0; c0 < KEYS_PER_SPLIT; c0 += CHK) {
        CP_WAIT0();
        __syncthreads();   // stage ready; prev-chunk tiles free

        // ---- conversion: K from stage (LDS), V from gmem ----
        #pragma unroll
        for (int it = 0; it < 4; it++) {
            int idx = t + it*256;          // 1024 float4
            int key = idx >> 5, dq = idx & 31;
            float4 kv = stg4[idx];
            float4 vv = *(const float4*)(Vc +
                        ((size_t)(b*CL + key0 + c0 + key)*NKV + kvh)*HD + dq*4);
            uint32_t h0, l0, h1, l1;
            int o = key*AST + dq*4;
            split2(kv.x, kv.y, h0, l0); split2(kv.z, kv.w, h1, l1);
            *(uint32_t*)&khi[o] = h0;  *(uint32_t*)&khi[o+2] = h1;
            *(uint32_t*)&klo[o] = l0;  *(uint32_t*)&klo[o+2] = l1;
            split2(vv.x, vv.y, h0, l0); split2(vv.z, vv.w, h1, l1);
            *(uint32_t*)&vhi[o] = h0;  *(uint32_t*)&vhi[o+2] = h1;
            *(uint32_t*)&vlo[o] = l0;  *(uint32_t*)&vlo[o+2] = l1;
        }
        __syncthreads();   // tiles ready; stage consumed

        // ---- issue next chunk's K staging (overlaps with MMA phases) ----
        if (c0 + CHK < KEYS_PER_SPLIT) {
            #pragma unroll
            for (int it = 0; it < 4; it++) {
                int idx = t + it*256;
                int key = idx >> 5, dq = idx & 31;
                const float* src = Kc +
                    ((size_t)(b*CL + key0 + c0 + CHK + key)*NKV + kvh)*HD + dq*4;
                cpasync16(smb + O_STG + (uint32_t)idx*16, src);
            }
        }
        CP_COMMIT();

        // ---- QK: scores[64q][32keys], 3 products, K=128 (8 k16 steps) ----
        {
            float acc[2][4] = {};
            #pragma unroll
            for (int kk = 0; kk < 8; kk++) {
                const int kb = kk*16 + 2*tg;
                int ai = (m0 + g)*AST + kb;
                uint32_t ah0 = *(const uint32_t*)&qhi[ai];
                uint32_t ah1 = *(const uint32_t*)&qhi[ai + 8*AST];
                uint32_t ah2 = *(const uint32_t*)&qhi[ai + 8];
                uint32_t ah3 = *(const uint32_t*)&qhi[ai + 8*AST + 8];
                uint32_t al0 = *(const uint32_t*)&qlo[ai];
                uint32_t al1 = *(const uint32_t*)&qlo[ai + 8*AST];
                uint32_t al2 = *(const uint32_t*)&qlo[ai + 8];
                uint32_t al3 = *(const uint32_t*)&qlo[ai + 8*AST + 8];
                #pragma unroll
                for (int nf = 0; nf < 2; nf++) {
                    int bi = (wn*16 + nf*8 + g)*AST + kb;
                    uint32_t bh0 = *(const uint32_t*)&khi[bi];
                    uint32_t bh1 = *(const uint32_t*)&khi[bi + 8];
                    uint32_t bl0 = *(const uint32_t*)&klo[bi];
                    uint32_t bl1 = *(const uint32_t*)&klo[bi + 8];
                    MMA_BF16(acc[nf], ah0, ah1, ah2, ah3, bh0, bh1);
                    MMA_BF16(acc[nf], ah0, ah1, ah2, ah3, bl0, bl1);
                    MMA_BF16(acc[nf], al0, al1, al2, al3, bh0, bh1);
                }
            }
            #pragma unroll
            for (int nf = 0; nf < 2; nf++) {
                int col = wn*16 + nf*8 + 2*tg;
                float2 lo2 = { acc[nf][0], acc[nf][1] };
                float2 hi2 = { acc[nf][2], acc[nf][3] };
                *(float2*)&s_t[(m0+g)*36 + col]   = lo2;
                *(float2*)&s_t[(m0+g+8)*36 + col] = hi2;
            }
        }
        __syncthreads();

        // ---- online softmax (warp w -> rows w*8..w*8+7), P -> bf16 hi/lo ----
        #pragma unroll
        for (int rr = 0; rr < 8; rr++) {
            int q = wid*8 + rr;
            int s = q & 15;
            float v0 = s_t[q*36 + lane] + mask[(size_t)s*CL + key0 + c0 + lane];
            float mx = v0;
            #pragma unroll
            for (int o = 16; o; o >>= 1) mx = fmaxf(mx, __shfl_xor_sync(0xffffffffu, mx, o));
            float mnew = fmaxf(m_s[q], mx);
            float p0 = __expf(v0 - mnew);
            uint32_t u0 = __float_as_uint(p0);
            float h0 = __uint_as_float(u0 & 0xFFFF0000u);
            phi[q*PST + lane] = (uint16_t)(u0 >> 16);
            plo[q*PST + lane] = (uint16_t)(__float_as_uint(p0 - h0) >> 16);
            float sum = p0;
            #pragma unroll
            for (int o = 16; o; o >>= 1) sum += __shfl_xor_sync(0xffffffffu, sum, o);
            if (lane == 0) {
                float sc = __expf(m_s[q] - mnew);
                sc_s[q] = sc;
                l_s[q]  = l_s[q] * sc + sum;
                m_s[q]  = mnew;
            }
        }
        __syncthreads();

        // ---- PV: O[64q][128d] += P @ V, 3 products, k=32 (2 k16 steps) ----
        {
            float sc0 = sc_s[m0 + g];
            float sc1 = sc_s[m0 + g + 8];
            #pragma unroll
            for (int nf = 0; nf < 8; nf++) {
                accO[nf][0] *= sc0; accO[nf][1] *= sc0;
                accO[nf][2] *= sc1; accO[nf][3] *= sc1;
            }
            #pragma unroll
            for (int kk = 0; kk < 2; kk++) {
                const int kb = kk*16 + 2*tg;
                int ai = (m0 + g)*PST + kb;
                uint32_t ah0 = *(const uint32_t*)&phi[ai];
                uint32_t ah1 = *(const uint32_t*)&phi[ai + 8*PST];
                uint32_t ah2 = *(const uint32_t*)&phi[ai + 8];
                uint32_t ah3 = *(const uint32_t*)&phi[ai + 8*PST + 8];
                uint32_t al0 = *(const uint32_t*)&plo[ai];
                uint32_t al1 = *(const uint32_t*)&plo[ai + 8*PST];
                uint32_t al2 = *(const uint32_t*)&plo[ai + 8];
                uint32_t al3 = *(const uint32_t*)&plo[ai + 8*PST + 8];
                #pragma unroll
                for (int dd = 0; dd < 4; dd++) {
                    int d0 = wn*64 + dd*16;
                    uint32_t rowa = (uint32_t)((kk*16 + (lane & 15))*AST
                                    + d0 + (lane >> 4)*8) * 2u;
                    uint32_t bh0, bh1, bh2, bh3, bl0, bl1, bl2, bl3;
                    ldmx4t(bh0, bh1, bh2, bh3, smb + O_VHI + rowa);
                    ldmx4t(bl0, bl1, bl2, bl3, smb + O_VLO + rowa);
                    MMA_BF16(accO[dd*2],   ah0, ah1, ah2, ah3, bh0, bh1);
                    MMA_BF16(accO[dd*2],   al0, al1, al2, al3, bh0, bh1);
                    MMA_BF16(accO[dd*2],   ah0, ah1, ah2, ah3, bl0, bl1);
                    MMA_BF16(accO[dd*2+1], ah0, ah1, ah2, ah3, bh2, bh3);
                    MMA_BF16(accO[dd*2+1], al0, al1, al2, al3, bh2, bh3);
                    MMA_BF16(accO[dd*2+1], ah0, ah1, ah2, ah3, bl2, bl3);
                }
            }
        }
        // (loop-top __syncthreads covers tile reuse)
    }

    // ---- write partials ----
    size_t base = ((size_t)(b*NKV + kvh)*NSPLIT + sp)*64;
    #pragma unroll
    for (int nf = 0; nf < 8; nf++) {
        int col = wn*64 + nf*8 + 2*tg;
        float2 lo2 = { accO[nf][0], accO[nf][1] };
        float2 hi2 = { accO[nf][2], accO[nf][3] };
        *(float2*)&po[(base + m0 + g)*128 + col]     = lo2;
        *(float2*)&po[(base + m0 + g + 8)*128 + col] = hi2;
    }
    if (t < 64) {
        pml[(base + t)*2 + 0] = m_s[t];
        pml[(base + t)*2 + 1] = l_s[t];
    }
}

// ---------------------------------------------------------------------------
// Combine split-KV partials -> attn output.  grid (64, 4): bk x d-slice.
// ---------------------------------------------------------------------------
__global__ __launch_bounds__(256) void attn_combine(
    const float* __restrict__ po, const float* __restrict__ pml,
    float* __restrict__ attn_out)
{
    __shared__ float wsm[NSPLIT][64];
    __shared__ float linv[64];
    const int t  = threadIdx.x;
    const int bk = blockIdx.x;           // b*NKV + kvh
    if (t < 64) {
        float mv[NSPLIT];
        float M = -1e30f;
        #pragma unroll
        for (int i = 0; i < NSPLIT; i++) {
            mv[i] = pml[((size_t)(bk*NSPLIT + i)*64 + t)*2 + 0];
            M = fmaxf(M, mv[i]);
        }
        float L = 0.f;
        #pragma unroll
        for (int i = 0; i < NSPLIT; i++) {
            float w = __expf(mv[i] - M);
            wsm[i][t] = w;
            L += w * pml[((size_t)(bk*NSPLIT + i)*64 + t)*2 + 1];
        }
        linv[t] = 1.f / L;
    }
    __syncthreads();
    const int dq   = blockIdx.y*32 + (t & 31);  // d in 0..127
    const int qrow = t >> 5;                    // 0..7
    const int b = bk >> 3, kvh = bk & 7;
    for (int q = qrow; q < 64; q += 8) {
        float o = 0.f;
        #pragma unroll
        for (int i = 0; i < NSPLIT; i++)
            o += po[((size_t)(bk*NSPLIT + i)*64 + q)*128 + dq] * wsm[i][q];
        o *= linv[q];
        int s = q & 15, hh = q >> 4;
        attn_out[(size_t)(b*SEQ + s)*DIM + (kvh*4 + hh)*HD + dq] = o;
    }
}

// ---------------------------------------------------------------------------
extern "C" void kernel_launch(void* const* d_in, const int* in_sizes, int n_in,
                              void* d_out, int out_size)
{
    const float* x     = (const float*)d_in[0];
    const float* mask  = (const float*)d_in[1];
    const float* freqs = (const float*)d_in[2];
    const float* ck    = (const float*)d_in[3];
    const float* cv    = (const float*)d_in[4];
    const float* wq    = (const float*)d_in[5];
    const float* wk    = (const float*)d_in[6];
    const float* wv    = (const float*)d_in[7];
    const float* wo    = (const float*)d_in[8];
    float* out = (float*)d_out;

    float *qkv, *attn, *po, *pml;
    cudaGetSymbolAddress((void**)&qkv,  g_qkv);
    cudaGetSymbolAddress((void**)&attn, g_attn);
    cudaGetSymbolAddress((void**)&po,   g_po);
    cudaGetSymbolAddress((void**)&pml,  g_pml);

    const int GEMM_SMEM64 = (2*128*ASTR + 2*64*ASTR) * 2;   // 55296
    const int GEMM_SMEM32 = (2*128*ASTR + 2*32*ASTR) * 2;   // 46080
    static int smem_set = 0;
    if (!smem_set) {
        cudaFuncSetAttribute(gemm_mma<64>, cudaFuncAttributeMaxDynamicSharedMemorySize, GEMM_SMEM64);
        cudaFuncSetAttribute(gemm_mma<32>, cudaFuncAttributeMaxDynamicSharedMemorySize, GEMM_SMEM32);
        cudaFuncSetAttribute(attn_mma, cudaFuncAttributeMaxDynamicSharedMemorySize, ATTN_SMEM);
        smem_set = 1;
    }

    // Fused QKV projection (bf16 mma.sync, split hi+lo) + RoPE epilogue
    gemm_mma<64><<<NQKV/64, 256, GEMM_SMEM64>>>(x, wq, wk, wv, qkv, NQKV, freqs, ROPE_LIM);

    // Cache shift + append (K and V in one launch)
    int cb = (CACHE_ELEMS/4 + 255) / 256;
    cache_update2<<<dim3(cb, 2), 256>>>(ck, cv, out + CK_OFF, out + CV_OFF, qkv);

    // Attention (split-KV, tensor core, cp.async K staging) + combine
    attn_mma<<<dim3(NSPLIT, NKV, BSZ), 256, ATTN_SMEM>>>(
        qkv, out + CK_OFF, out + CV_OFF, mask, po, pml);
    attn_combine<<<dim3(BSZ*NKV, 4), 256>>>(po, pml, attn);

    // Output projection (bf16 mma.sync, BN=32 for 128-block launch width)
    gemm_mma<32><<<DIM/32, 256, GEMM_SMEM32>>>(attn, wo, nullptr, nullptr, out, DIM, nullptr, 0);
}

// round 11
// speedup vs baseline: 4.1363x; 1.1403x over previous
#include <cuda_runtime.h>
#include <cstdint>

#define BSZ 8
#define SEQ 16
#define DIM 4096
#define NH 32
#define NKV 8
#define HD 128
#define CL 4096
#define NT (BSZ*SEQ)                 // 128 tokens
#define NQKV (DIM + 2*NKV*HD)        // 6144
#define ROPE_LIM (DIM + NKV*HD)      // 5120
#define CACHE_ELEMS (BSZ*CL*NKV*HD)
#define CK_OFF ((size_t)NT*DIM)
#define CV_OFF (CK_OFF + CACHE_ELEMS)
#define RSQRT_HD 0.08838834764831845f
#define NSPLIT 8
#define KEYS_PER_SPLIT (CL/NSPLIT)   // 512

typedef unsigned long long ull;

__device__ float g_qkv[(size_t)NT*NQKV];
__device__ float g_attn[(size_t)NT*DIM];
__device__ float g_po[(size_t)BSZ*NKV*NSPLIT*64*128];
__device__ float g_pml[(size_t)BSZ*NKV*NSPLIT*64*2];

// ---- bf16 mma.sync (baseline sm_80+ ISA) ----------------------------------
#define MMA_BF16(d, a0,a1,a2,a3, b0,b1) \
    asm volatile( \
        "mma.sync.aligned.m16n8k16.row.col.f32.bf16.bf16.f32 " \
        "{%0,%1,%2,%3}, {%4,%5,%6,%7}, {%8,%9}, {%0,%1,%2,%3};" \
        : "+f"(d[0]), "+f"(d[1]), "+f"(d[2]), "+f"(d[3]) \
        : "r"(a0), "r"(a1), "r"(a2), "r"(a3), "r"(b0), "r"(b1))

__device__ __forceinline__ void ldmx4t(uint32_t& r0, uint32_t& r1,
                                       uint32_t& r2, uint32_t& r3, uint32_t addr) {
    asm volatile("ldmatrix.sync.aligned.m8n8.x4.trans.shared.b16 {%0,%1,%2,%3}, [%4];"
        : "=r"(r0), "=r"(r1), "=r"(r2), "=r"(r3) : "r"(addr));
}
__device__ __forceinline__ uint32_t smem_u32(const void* p) {
    uint32_t a;
    asm("{ .reg .u64 t; cvta.to.shared.u64 t, %1; cvt.u32.u64 %0, t; }"
        : "=r"(a) : "l"(p));
    return a;
}
__device__ __forceinline__ void cpasync16(uint32_t dst, const void* src) {
    asm volatile("cp.async.cg.shared.global [%0], [%1], 16;"
                 :: "r"(dst), "l"(src) : "memory");
}
#define CP_COMMIT() asm volatile("cp.async.commit_group;" ::: "memory")
#define CP_WAIT0()  asm volatile("cp.async.wait_group 0;" ::: "memory")

// split one float pair -> (hi bf16x2, lo bf16x2); first element in low half
__device__ __forceinline__ void split2(float x, float y, uint32_t& hi, uint32_t& lo) {
    uint32_t ux = __float_as_uint(x), uy = __float_as_uint(y);
    float hx = __uint_as_float(ux & 0xFFFF0000u);
    float hy = __uint_as_float(uy & 0xFFFF0000u);
    hi = __byte_perm(ux, uy, 0x7632);
    lo = __byte_perm(__float_as_uint(x - hx), __float_as_uint(y - hy), 0x7632);
}

// ---------------------------------------------------------------------------
// Tensor-core GEMM (split-bf16 mma.sync), templated on BN (64 or 32).
// ---------------------------------------------------------------------------
#define BKS 64
#define NSTG (DIM/BKS)          // 64
#define ASTR 72
#define U16_AHI 0
#define U16_ALO (128*ASTR)
#define U16_WHI (2*128*ASTR)

template<int BN>
__global__ __launch_bounds__(256) void gemm_mma(
    const float* __restrict__ A,
    const float* __restrict__ W0, const float* __restrict__ W1,
    const float* __restrict__ W2,
    float* __restrict__ C, int ldc,
    const float* __restrict__ freqs, int ropeLim)
{
    extern __shared__ char smraw[];
    uint16_t* sm16 = (uint16_t*)smraw;
    constexpr int MH = BN / 32;
    constexpr int WLO = 2*128*ASTR + BN*ASTR;

    const int t    = threadIdx.x;
    const int wid  = t >> 5;
    const int lane = t & 31;
    const int g    = lane >> 2;
    const int tg   = lane & 3;
    const int wm   = (BN == 64) ? (wid >> 1) : wid;
    const int wn   = (BN == 64) ? (wid & 1) : 0;
    const int n0   = blockIdx.x * BN;

    const float* W = W0; int nr = n0;
    if (W1 != nullptr && n0 >= DIM) {
        if (n0 < DIM + NKV*HD) { W = W1; nr = n0 - DIM; }
        else                   { W = W2; nr = n0 - DIM - NKV*HD; }
    }

    float acc[MH][4][4] = {};
    float4 pa[8], pw[BN/16];

    #pragma unroll
    for (int it = 0; it < 8; it++) {
        int v = t + it*256, row = v >> 4, gq = v & 15;
        pa[it] = *(const float4*)(A + (size_t)row * DIM + gq*4);
    }
    #pragma unroll
    for (int it = 0; it < BN/16; it++) {
        int v = t + it*256, row = v >> 4, gq = v & 15;
        pw[it] = *(const float4*)(W + (size_t)(nr + row) * DIM + gq*4);
    }

    for (int st = 0; st < NSTG; st++) {
        __syncthreads();
        #pragma unroll
        for (int it = 0; it < 8; it++) {
            int v = t + it*256, row = v >> 4, gq = v & 15;
            int idx = row*ASTR + gq*4;
            uint32_t h0, l0, h1, l1;
            split2(pa[it].x, pa[it].y, h0, l0);
            split2(pa[it].z, pa[it].w, h1, l1);
            *(uint32_t*)&sm16[U16_AHI + idx]     = h0;
            *(uint32_t*)&sm16[U16_AHI + idx + 2] = h1;
            *(uint32_t*)&sm16[U16_ALO + idx]     = l0;
            *(uint32_t*)&sm16[U16_ALO + idx + 2] = l1;
        }
        #pragma unroll
        for (int it = 0; it < BN/16; it++) {
            int v = t + it*256, row = v >> 4, gq = v & 15;
            int idx = row*ASTR + gq*4;
            uint32_t h0, l0, h1, l1;
            split2(pw[it].x, pw[it].y, h0, l0);
            split2(pw[it].z, pw[it].w, h1, l1);
            *(uint32_t*)&sm16[U16_WHI + idx]     = h0;
            *(uint32_t*)&sm16[U16_WHI + idx + 2] = h1;
            *(uint32_t*)&sm16[WLO + idx]     = l0;
            *(uint32_t*)&sm16[WLO + idx + 2] = l1;
        }
        __syncthreads();

        if (st + 1 < NSTG) {
            const int k0 = (st + 1) * BKS;
            #pragma unroll
            for (int it = 0; it < 8; it++) {
                int v = t + it*256, row = v >> 4, gq = v & 15;
                pa[it] = *(const float4*)(A + (size_t)row * DIM + k0 + gq*4);
            }
            #pragma unroll
            for (int it = 0; it < BN/16; it++) {
                int v = t + it*256, row = v >> 4, gq = v & 15;
                pw[it] = *(const float4*)(W + (size_t)(nr + row) * DIM + k0 + gq*4);
            }
        }

        #pragma unroll
        for (int kk = 0; kk < 4; kk++) {
            const int kb = kk*16 + 2*tg;
            uint32_t bh0[4], bh1[4], bl0[4], bl1[4];
            #pragma unroll
            for (int nt = 0; nt < 4; nt++) {
                int bi = (wn*32 + nt*8 + g)*ASTR + kb;
                bh0[nt] = *(const uint32_t*)&sm16[U16_WHI + bi];
                bh1[nt] = *(const uint32_t*)&sm16[U16_WHI + bi + 8];
                bl0[nt] = *(const uint32_t*)&sm16[WLO + bi];
                bl1[nt] = *(const uint32_t*)&sm16[WLO + bi + 8];
            }
            #pragma unroll
            for (int mh = 0; mh < MH; mh++) {
                int ai = (wm*16*MH + mh*16 + g)*ASTR + kb;
                uint32_t ah0 = *(const uint32_t*)&sm16[U16_AHI + ai];
                uint32_t ah1 = *(const uint32_t*)&sm16[U16_AHI + ai + 8*ASTR];
                uint32_t ah2 = *(const uint32_t*)&sm16[U16_AHI + ai + 8];
                uint32_t ah3 = *(const uint32_t*)&sm16[U16_AHI + ai + 8*ASTR + 8];
                uint32_t al0 = *(const uint32_t*)&sm16[U16_ALO + ai];
                uint32_t al1 = *(const uint32_t*)&sm16[U16_ALO + ai + 8*ASTR];
                uint32_t al2 = *(const uint32_t*)&sm16[U16_ALO + ai + 8];
                uint32_t al3 = *(const uint32_t*)&sm16[U16_ALO + ai + 8*ASTR + 8];
                #pragma unroll
                for (int nt = 0; nt < 4; nt++) {
                    MMA_BF16(acc[mh][nt], ah0, ah1, ah2, ah3, bh0[nt], bh1[nt]);
                    MMA_BF16(acc[mh][nt], ah0, ah1, ah2, ah3, bl0[nt], bl1[nt]);
                    MMA_BF16(acc[mh][nt], al0, al1, al2, al3, bh0[nt], bh1[nt]);
                }
            }
        }
    }

    const bool doRope = n0 < ropeLim;
    #pragma unroll
    for (int mh = 0; mh < MH; mh++) {
        #pragma unroll
        for (int nt = 0; nt < 4; nt++) {
            int r0 = wm*16*MH + mh*16 + g;
            int r1 = r0 + 8;
            int gc = n0 + wn*32 + nt*8 + 2*tg;
            float v0 = acc[mh][nt][0], v1 = acc[mh][nt][1];
            float v2 = acc[mh][nt][2], v3 = acc[mh][nt][3];
            float2 o0, o1;
            if (doRope) {
                int pd2 = (gc & (HD-1)) >> 1;
                const float* f0 = freqs + (r0 & (SEQ-1))*128 + pd2*2;
                const float* f1 = freqs + (r1 & (SEQ-1))*128 + pd2*2;
                float ca0 = f0[0], sa0 = f0[1];
                float ca1 = f1[0], sa1 = f1[1];
                o0.x = v0*ca0 - v1*sa0;  o0.y = v0*sa0 + v1*ca0;
                o1.x = v2*ca1 - v3*sa1;  o1.y = v2*sa1 + v3*ca1;
            } else {
                o0.x = v0; o0.y = v1; o1.x = v2; o1.y = v3;
            }
            *(float2*)&C[(size_t)r0 * ldc + gc] = o0;
            *(float2*)&C[(size_t)r1 * ldc + gc] = o1;
        }
    }
}

// ---------------------------------------------------------------------------
// Attention + fused cache write. grid (NSPLIT, NKV, BSZ), 256 threads.
// Reads shifted old cache / new RoPE'd k,v; writes out caches; computes attn.
// ---------------------------------------------------------------------------
#define AST 136     // u16 stride for 128-wide tiles (q, K, V)
#define PST 40      // u16 stride for P (32 keys)
#define CHK 32

#define O_QHI 0
#define O_QLO (O_QHI + 17408)
#define O_KHI (O_QLO + 17408)
#define O_KLO (O_KHI + 8704)
#define O_VHI (O_KLO + 8704)
#define O_VLO (O_VHI + 8704)
#define O_ST  (O_VLO + 8704)      // f32 [64][36]
#define O_PHI (O_ST  + 9216)      // u16 [64][40]
#define O_PLO (O_PHI + 5120)
#define O_MS  (O_PLO + 5120)
#define O_LS  (O_MS  + 256)
#define O_SCS (O_LS  + 256)
#define O_STG (O_SCS + 256)       // raw fp32 K stage: 32*128*4 = 16384
#define ATTN_SMEM (O_STG + 16384) // 106496 bytes -> 2 CTAs/SM

__global__ __launch_bounds__(256, 2) void attn_mma(
    const float* __restrict__ qkv,
    const float* __restrict__ ckin, const float* __restrict__ cvin,
    float* __restrict__ outK, float* __restrict__ outV,
    const float* __restrict__ mask,
    float* __restrict__ po, float* __restrict__ pml)
{
    extern __shared__ char sm[];
    uint16_t* qhi = (uint16_t*)(sm + O_QHI);
    uint16_t* qlo = (uint16_t*)(sm + O_QLO);
    uint16_t* khi = (uint16_t*)(sm + O_KHI);
    uint16_t* klo = (uint16_t*)(sm + O_KLO);
    uint16_t* vhi = (uint16_t*)(sm + O_VHI);
    uint16_t* vlo = (uint16_t*)(sm + O_VLO);
    float*    s_t = (float*)(sm + O_ST);
    uint16_t* phi = (uint16_t*)(sm + O_PHI);
    uint16_t* plo = (uint16_t*)(sm + O_PLO);
    float*    m_s = (float*)(sm + O_MS);
    float*    l_s = (float*)(sm + O_LS);
    float*    sc_s= (float*)(sm + O_SCS);
    const float4* stg4 = (const float4*)(sm + O_STG);
    const uint32_t smb = smem_u32(sm);

    const int t    = threadIdx.x;
    const int wid  = t >> 5;
    const int lane = t & 31;
    const int g    = lane >> 2;
    const int tg   = lane & 3;
    const int wm   = wid >> 1;
    const int wn   = wid & 1;
    const int m0   = wm * 16;
    const int sp   = blockIdx.x;
    const int kvh  = blockIdx.y;
    const int b    = blockIdx.z;
    const int key0 = sp * KEYS_PER_SPLIT;

    // source pointer for cache position kpos (shifted old cache or new k/v)
    auto ksrc = [&](int kpos) -> const float* {
        if (kpos < CL - SEQ)
            return ckin + ((size_t)(b*CL + kpos + SEQ)*NKV + kvh)*HD;
        return qkv + (size_t)(b*SEQ + (kpos - (CL - SEQ)))*NQKV + DIM + kvh*HD;
    };
    auto vsrc = [&](int kpos) -> const float* {
        if (kpos < CL - SEQ)
            return cvin + ((size_t)(b*CL + kpos + SEQ)*NKV + kvh)*HD;
        return qkv + (size_t)(b*SEQ + (kpos - (CL - SEQ)))*NQKV + DIM + NKV*HD + kvh*HD;
    };

    // ---- q load + scale + split (once per block) ----
    #pragma unroll
    for (int it = 0; it < 8; it++) {
        int idx = t + it*256;
        int q = idx >> 5, dq = idx & 31;
        const float* src = qkv + (size_t)(b*SEQ + (q & 15))*NQKV
                           + (kvh*4 + (q >> 4))*HD + dq*4;
        float4 v = *(const float4*)src;
        v.x *= RSQRT_HD; v.y *= RSQRT_HD; v.z *= RSQRT_HD; v.w *= RSQRT_HD;
        uint32_t h0, l0, h1, l1;
        split2(v.x, v.y, h0, l0);
        split2(v.z, v.w, h1, l1);
        int o = q*AST + dq*4;
        *(uint32_t*)&qhi[o] = h0;   *(uint32_t*)&qhi[o+2] = h1;
        *(uint32_t*)&qlo[o] = l0;   *(uint32_t*)&qlo[o+2] = l1;
    }
    if (t < 64) { m_s[t] = -1e30f; l_s[t] = 0.f; }

    // ---- prologue: stage chunk 0's K via cp.async (from shifted sources) ----
    #pragma unroll
    for (int it = 0; it < 4; it++) {
        int idx = t + it*256;
        int key = idx >> 5, dq = idx & 31;
        cpasync16(smb + O_STG + (uint32_t)idx*16, ksrc(key0 + key) + dq*4);
    }
    CP_COMMIT();

    float accO[8][4] = {};

    for (int c0 = 0; c0 < KEYS_PER_SPLIT; c0 += CHK) {
        CP_WAIT0();
        __syncthreads();

        // ---- conversion + cache write-out ----
        #pragma unroll
        for (int it = 0; it < 4; it++) {
            int idx = t + it*256;
            int key = idx >> 5, dq = idx & 31;
            int kpos = key0 + c0 + key;
            float4 kv = stg4[idx];
            float4 vv = *(const float4*)(vsrc(kpos) + dq*4);
            size_t oofs = ((size_t)(b*CL + kpos)*NKV + kvh)*HD + dq*4;
            *(float4*)(outK + oofs) = kv;
            *(float4*)(outV + oofs) = vv;
            uint32_t h0, l0, h1, l1;
            int o = key*AST + dq*4;
            split2(kv.x, kv.y, h0, l0); split2(kv.z, kv.w, h1, l1);
            *(uint32_t*)&khi[o] = h0;  *(uint32_t*)&khi[o+2] = h1;
            *(uint32_t*)&klo[o] = l0;  *(uint32_t*)&klo[o+2] = l1;
            split2(vv.x, vv.y, h0, l0); split2(vv.z, vv.w, h1, l1);
            *(uint32_t*)&vhi[o] = h0;  *(uint32_t*)&vhi[o+2] = h1;
            *(uint32_t*)&vlo[o] = l0;  *(uint32_t*)&vlo[o+2] = l1;
        }
        __syncthreads();

        // ---- issue next chunk's K staging (overlaps with MMA phases) ----
        if (c0 + CHK < KEYS_PER_SPLIT) {
            #pragma unroll
            for (int it = 0; it < 4; it++) {
                int idx = t + it*256;
                int key = idx >> 5, dq = idx & 31;
                cpasync16(smb + O_STG + (uint32_t)idx*16,
                          ksrc(key0 + c0 + CHK + key) + dq*4);
            }
        }
        CP_COMMIT();

        // ---- QK: scores[64q][32keys], 3 products, K=128 (8 k16 steps) ----
        {
            float acc[2][4] = {};
            #pragma unroll
            for (int kk = 0; kk < 8; kk++) {
                const int kb = kk*16 + 2*tg;
                int ai = (m0 + g)*AST + kb;
                uint32_t ah0 = *(const uint32_t*)&qhi[ai];
                uint32_t ah1 = *(const uint32_t*)&qhi[ai + 8*AST];
                uint32_t ah2 = *(const uint32_t*)&qhi[ai + 8];
                uint32_t ah3 = *(const uint32_t*)&qhi[ai + 8*AST + 8];
                uint32_t al0 = *(const uint32_t*)&qlo[ai];
                uint32_t al1 = *(const uint32_t*)&qlo[ai + 8*AST];
                uint32_t al2 = *(const uint32_t*)&qlo[ai + 8];
                uint32_t al3 = *(const uint32_t*)&qlo[ai + 8*AST + 8];
                #pragma unroll
                for (int nf = 0; nf < 2; nf++) {
                    int bi = (wn*16 + nf*8 + g)*AST + kb;
                    uint32_t bh0 = *(const uint32_t*)&khi[bi];
                    uint32_t bh1 = *(const uint32_t*)&khi[bi + 8];
                    uint32_t bl0 = *(const uint32_t*)&klo[bi];
                    uint32_t bl1 = *(const uint32_t*)&klo[bi + 8];
                    MMA_BF16(acc[nf], ah0, ah1, ah2, ah3, bh0, bh1);
                    MMA_BF16(acc[nf], ah0, ah1, ah2, ah3, bl0, bl1);
                    MMA_BF16(acc[nf], al0, al1, al2, al3, bh0, bh1);
                }
            }
            #pragma unroll
            for (int nf = 0; nf < 2; nf++) {
                int col = wn*16 + nf*8 + 2*tg;
                float2 lo2 = { acc[nf][0], acc[nf][1] };
                float2 hi2 = { acc[nf][2], acc[nf][3] };
                *(float2*)&s_t[(m0+g)*36 + col]   = lo2;
                *(float2*)&s_t[(m0+g+8)*36 + col] = hi2;
            }
        }
        __syncthreads();

        // ---- online softmax, P -> bf16 hi/lo ----
        #pragma unroll
        for (int rr = 0; rr < 8; rr++) {
            int q = wid*8 + rr;
            int s = q & 15;
            float v0 = s_t[q*36 + lane] + mask[(size_t)s*CL + key0 + c0 + lane];
            float mx = v0;
            #pragma unroll
            for (int o = 16; o; o >>= 1) mx = fmaxf(mx, __shfl_xor_sync(0xffffffffu, mx, o));
            float mnew = fmaxf(m_s[q], mx);
            float p0 = __expf(v0 - mnew);
            uint32_t u0 = __float_as_uint(p0);
            float h0 = __uint_as_float(u0 & 0xFFFF0000u);
            phi[q*PST + lane] = (uint16_t)(u0 >> 16);
            plo[q*PST + lane] = (uint16_t)(__float_as_uint(p0 - h0) >> 16);
            float sum = p0;
            #pragma unroll
            for (int o = 16; o; o >>= 1) sum += __shfl_xor_sync(0xffffffffu, sum, o);
            if (lane == 0) {
                float sc = __expf(m_s[q] - mnew);
                sc_s[q] = sc;
                l_s[q]  = l_s[q] * sc + sum;
                m_s[q]  = mnew;
            }
        }
        __syncthreads();

        // ---- PV: O[64q][128d] += P @ V, 3 products, k=32 (2 k16 steps) ----
        {
            float sc0 = sc_s[m0 + g];
            float sc1 = sc_s[m0 + g + 8];
            #pragma unroll
            for (int nf = 0; nf < 8; nf++) {
                accO[nf][0] *= sc0; accO[nf][1] *= sc0;
                accO[nf][2] *= sc1; accO[nf][3] *= sc1;
            }
            #pragma unroll
            for (int kk = 0; kk < 2; kk++) {
                const int kb = kk*16 + 2*tg;
                int ai = (m0 + g)*PST + kb;
                uint32_t ah0 = *(const uint32_t*)&phi[ai];
                uint32_t ah1 = *(const uint32_t*)&phi[ai + 8*PST];
                uint32_t ah2 = *(const uint32_t*)&phi[ai + 8];
                uint32_t ah3 = *(const uint32_t*)&phi[ai + 8*PST + 8];
                uint32_t al0 = *(const uint32_t*)&plo[ai];
                uint32_t al1 = *(const uint32_t*)&plo[ai + 8*PST];
                uint32_t al2 = *(const uint32_t*)&plo[ai + 8];
                uint32_t al3 = *(const uint32_t*)&plo[ai + 8*PST + 8];
                #pragma unroll
                for (int dd = 0; dd < 4; dd++) {
                    int d0 = wn*64 + dd*16;
                    uint32_t rowa = (uint32_t)((kk*16 + (lane & 15))*AST
                                    + d0 + (lane >> 4)*8) * 2u;
                    uint32_t bh0, bh1, bh2, bh3, bl0, bl1, bl2, bl3;
                    ldmx4t(bh0, bh1, bh2, bh3, smb + O_VHI + rowa);
                    ldmx4t(bl0, bl1, bl2, bl3, smb + O_VLO + rowa);
                    MMA_BF16(accO[dd*2],   ah0, ah1, ah2, ah3, bh0, bh1);
                    MMA_BF16(accO[dd*2],   al0, al1, al2, al3, bh0, bh1);
                    MMA_BF16(accO[dd*2],   ah0, ah1, ah2, ah3, bl0, bl1);
                    MMA_BF16(accO[dd*2+1], ah0, ah1, ah2, ah3, bh2, bh3);
                    MMA_BF16(accO[dd*2+1], al0, al1, al2, al3, bh2, bh3);
                    MMA_BF16(accO[dd*2+1], ah0, ah1, ah2, ah3, bl2, bl3);
                }
            }
        }
    }

    // ---- write partials ----
    size_t base = ((size_t)(b*NKV + kvh)*NSPLIT + sp)*64;
    #pragma unroll
    for (int nf = 0; nf < 8; nf++) {
        int col = wn*64 + nf*8 + 2*tg;
        float2 lo2 = { accO[nf][0], accO[nf][1] };
        float2 hi2 = { accO[nf][2], accO[nf][3] };
        *(float2*)&po[(base + m0 + g)*128 + col]     = lo2;
        *(float2*)&po[(base + m0 + g + 8)*128 + col] = hi2;
    }
    if (t < 64) {
        pml[(base + t)*2 + 0] = m_s[t];
        pml[(base + t)*2 + 1] = l_s[t];
    }
}

// ---------------------------------------------------------------------------
// Combine split-KV partials -> attn output.  grid (64, 4): bk x d-slice.
// ---------------------------------------------------------------------------
__global__ __launch_bounds__(256) void attn_combine(
    const float* __restrict__ po, const float* __restrict__ pml,
    float* __restrict__ attn_out)
{
    __shared__ float wsm[NSPLIT][64];
    __shared__ float linv[64];
    const int t  = threadIdx.x;
    const int bk = blockIdx.x;
    if (t < 64) {
        float mv[NSPLIT];
        float M = -1e30f;
        #pragma unroll
        for (int i = 0; i < NSPLIT; i++) {
            mv[i] = pml[((size_t)(bk*NSPLIT + i)*64 + t)*2 + 0];
            M = fmaxf(M, mv[i]);
        }
        float L = 0.f;
        #pragma unroll
        for (int i = 0; i < NSPLIT; i++) {
            float w = __expf(mv[i] - M);
            wsm[i][t] = w;
            L += w * pml[((size_t)(bk*NSPLIT + i)*64 + t)*2 + 1];
        }
        linv[t] = 1.f / L;
    }
    __syncthreads();
    const int dq   = blockIdx.y*32 + (t & 31);
    const int qrow = t >> 5;
    const int b = bk >> 3, kvh = bk & 7;
    for (int q = qrow; q < 64; q += 8) {
        float o = 0.f;
        #pragma unroll
        for (int i = 0; i < NSPLIT; i++)
            o += po[((size_t)(bk*NSPLIT + i)*64 + q)*128 + dq] * wsm[i][q];
        o *= linv[q];
        int s = q & 15, hh = q >> 4;
        attn_out[(size_t)(b*SEQ + s)*DIM + (kvh*4 + hh)*HD + dq] = o;
    }
}

// ---------------------------------------------------------------------------
extern "C" void kernel_launch(void* const* d_in, const int* in_sizes, int n_in,
                              void* d_out, int out_size)
{
    const float* x     = (const float*)d_in[0];
    const float* mask  = (const float*)d_in[1];
    const float* freqs = (const float*)d_in[2];
    const float* ck    = (const float*)d_in[3];
    const float* cv    = (const float*)d_in[4];
    const float* wq    = (const float*)d_in[5];
    const float* wk    = (const float*)d_in[6];
    const float* wv    = (const float*)d_in[7];
    const float* wo    = (const float*)d_in[8];
    float* out = (float*)d_out;

    float *qkv, *attn, *po, *pml;
    cudaGetSymbolAddress((void**)&qkv,  g_qkv);
    cudaGetSymbolAddress((void**)&attn, g_attn);
    cudaGetSymbolAddress((void**)&po,   g_po);
    cudaGetSymbolAddress((void**)&pml,  g_pml);

    const int GEMM_SMEM64 = (2*128*ASTR + 2*64*ASTR) * 2;
    const int GEMM_SMEM32 = (2*128*ASTR + 2*32*ASTR) * 2;
    static int smem_set = 0;
    if (!smem_set) {
        cudaFuncSetAttribute(gemm_mma<64>, cudaFuncAttributeMaxDynamicSharedMemorySize, GEMM_SMEM64);
        cudaFuncSetAttribute(gemm_mma<32>, cudaFuncAttributeMaxDynamicSharedMemorySize, GEMM_SMEM32);
        cudaFuncSetAttribute(attn_mma, cudaFuncAttributeMaxDynamicSharedMemorySize, ATTN_SMEM);
        smem_set = 1;
    }

    // Fused QKV projection + RoPE epilogue
    gemm_mma<64><<<NQKV/64, 256, GEMM_SMEM64>>>(x, wq, wk, wv, qkv, NQKV, freqs, ROPE_LIM);

    // Attention with fused cache shift+append writes, then combine
    attn_mma<<<dim3(NSPLIT, NKV, BSZ), 256, ATTN_SMEM>>>(
        qkv, ck, cv, out + CK_OFF, out + CV_OFF, mask, po, pml);
    attn_combine<<<dim3(BSZ*NKV, 4), 256>>>(po, pml, attn);

    // Output projection
    gemm_mma<32><<<DIM/32, 256, GEMM_SMEM32>>>(attn, wo, nullptr, nullptr, out, DIM, nullptr, 0);
}